// round 14
// baseline (speedup 1.0000x reference)
#include <cuda_runtime.h>
#include <cuda_fp16.h>
#include <math.h>
#include <stdint.h>

// Problem constants
#define E_MAX   320000
#define A_MAX   10000
#define B_DIM   4
#define NCH     64
#define HID     256
#define HAST    264   // half-element smem row stride (even, 8-half aligned)

// dist-MLP lookup table
#define TBL     1024
#define D_MAX   8.0f
#define DSTEP   (D_MAX / (float)TBL)
#define INV_STEP ((float)TBL / D_MAX)

// Scratch (static __device__; allocation APIs forbidden)
__device__ __align__(16) __half g_axH [B_DIM * A_MAX * NCH * 8];
__device__ __align__(16) __half g_tblP[TBL * NCH * 8];
__device__ __align__(16) float  g_enc [TBL * NCH];
__device__ __align__(16) float  g_tmpA[TBL * HID];
__device__ __align__(16) float  g_tmpB[TBL * HID];
__device__ __align__(16) float4 g_erec[E_MAX];   // sorted edge records {rx,ry,rz,dst}
__device__ int g_hist  [A_MAX];
__device__ int g_offs  [A_MAX + 1];
__device__ int g_cursor[A_MAX];

// ---------------------------------------------------------------------------
__device__ __forceinline__ float silu_fast(float v) {
    return v / (1.0f + __expf(-v));
}
__device__ __forceinline__ uint32_t pack_half2(float lo, float hi) {
    __half2 h = __floats2half2_rn(lo, hi);
    return *(uint32_t*)&h;
}

// ---------------------------------------------------------------------------
__global__ void zero_hist(int* __restrict__ hist, int A) {
    int t = blockIdx.x * blockDim.x + threadIdx.x;
    if (t < A) hist[t] = 0;
}

__global__ void convert_xv(const float* __restrict__ x_v, __half* __restrict__ axH,
                           int n) {
    int t = blockIdx.x * blockDim.x + threadIdx.x;
    if (t >= n) return;
    float vx = x_v[3 * t + 0];
    float vy = x_v[3 * t + 1];
    float vz = x_v[3 * t + 2];
    __half2* dp = (__half2*)(axH + (size_t)t * 8 + 4);
    dp[0] = __floats2half2_rn(vx, vy);
    dp[1] = __floats2half2_rn(vz, 0.0f);
}

__global__ void encode_table(float* __restrict__ enc) {
    int t = blockIdx.x * blockDim.x + threadIdx.x;
    if (t >= TBL * 64) return;
    int idx = t >> 6, j = t & 63;
    float d = (float)idx * DSTEP;
    int jj = (j < 32) ? j : (j - 32);
    float c = 0.31415926535897932f * (float)(1 + (jj >> 1));
    float ph = c * d;
    enc[t] = (j < 32) ? cosf(ph) : sinf(ph);
}

// ---------------------------------------------------------------------------
__global__ void hist_kernel(const int* __restrict__ src, int* __restrict__ hist, int E) {
    int e = blockIdx.x * blockDim.x + threadIdx.x;
    if (e < E) atomicAdd(&hist[src[e]], 1);
}

// shfl-based block scan, 1024 threads, chunked over A
__global__ void scan_kernel(const int* __restrict__ hist, int* __restrict__ offs,
                            int* __restrict__ cursor, int A) {
    __shared__ int wsum[32];
    __shared__ int carry_s;
    int tid = threadIdx.x, lane = tid & 31, wid = tid >> 5;
    if (tid == 0) { carry_s = 0; offs[0] = 0; }
    __syncthreads();
    for (int base = 0; base < A; base += 1024) {
        int i = base + tid;
        int v = (i < A) ? hist[i] : 0;
        int x = v;
#pragma unroll
        for (int d = 1; d < 32; d <<= 1) {
            int t = __shfl_up_sync(0xFFFFFFFFu, x, d);
            if (lane >= d) x += t;
        }
        if (lane == 31) wsum[wid] = x;
        __syncthreads();
        if (wid == 0) {
            int s = wsum[lane];
#pragma unroll
            for (int d = 1; d < 32; d <<= 1) {
                int t = __shfl_up_sync(0xFFFFFFFFu, s, d);
                if (lane >= d) s += t;
            }
            wsum[lane] = s;
        }
        __syncthreads();
        int woff = (wid > 0) ? wsum[wid - 1] : 0;
        int inc = carry_s + woff + x;
        if (i < A) { offs[i + 1] = inc; cursor[i] = inc - v; }
        __syncthreads();
        if (tid == 1023) carry_s = inc;
        __syncthreads();
    }
}

// scatter sorted edge records {rx, ry, rz, dst-as-float-bits}
__global__ void scatter_kernel(const int* __restrict__ src,
                               const int* __restrict__ dst,
                               const float* __restrict__ r_ij,
                               int* __restrict__ cursor,
                               float4* __restrict__ erec, int E) {
    int e = blockIdx.x * blockDim.x + threadIdx.x;
    if (e < E) {
        int p = atomicAdd(&cursor[src[e]], 1);
        float4 rec;
        rec.x = r_ij[3 * e + 0];
        rec.y = r_ij[3 * e + 1];
        rec.z = r_ij[3 * e + 2];
        rec.w = __int_as_float(dst[e]);
        erec[p] = rec;
    }
}

// ---------------------------------------------------------------------------
// fp32 SIMT GEMM for the table build: BM=16, BN=256, BK=32.
template <int K, bool SILU, bool HALF_OUT>
__global__ void __launch_bounds__(256) mlp_small(
    const float* __restrict__ A, const float* __restrict__ W,
    const float* __restrict__ bias, void* __restrict__ Cout, int M)
{
    constexpr int BM = 16, BK = 32;
    __shared__ float As[BM][BK + 1];
    __shared__ float Ws[BK][256];

    const int m0 = blockIdx.x * BM;
    const int tid = threadIdx.x;
    const int tx = tid & 63;
    const int ty = tid >> 6;

    float acc[4][4];
#pragma unroll
    for (int i = 0; i < 4; i++)
#pragma unroll
        for (int j = 0; j < 4; j++) acc[i][j] = 0.0f;

    for (int k0 = 0; k0 < K; k0 += BK) {
        {
            int r = tid >> 4, c2 = (tid & 15) * 2;
            int row = m0 + r;
            float2 v = (row < M) ? *(const float2*)&A[(size_t)row * K + k0 + c2]
                                 : make_float2(0.f, 0.f);
            As[r][c2] = v.x; As[r][c2 + 1] = v.y;
        }
#pragma unroll
        for (int s = 0; s < 8; s++) {
            int f4 = s * 256 + tid;
            int r = f4 >> 6, c4 = f4 & 63;
            float4 w = *(const float4*)&W[(size_t)(k0 + r) * 256 + c4 * 4];
            *(float4*)&Ws[r][c4 * 4] = w;
        }
        __syncthreads();

#pragma unroll
        for (int kk = 0; kk < BK; kk++) {
            float4 w = *(const float4*)&Ws[kk][tx * 4];
            float a0 = As[ty * 4 + 0][kk];
            float a1 = As[ty * 4 + 1][kk];
            float a2 = As[ty * 4 + 2][kk];
            float a3 = As[ty * 4 + 3][kk];
            acc[0][0] += a0 * w.x; acc[0][1] += a0 * w.y;
            acc[0][2] += a0 * w.z; acc[0][3] += a0 * w.w;
            acc[1][0] += a1 * w.x; acc[1][1] += a1 * w.y;
            acc[1][2] += a1 * w.z; acc[1][3] += a1 * w.w;
            acc[2][0] += a2 * w.x; acc[2][1] += a2 * w.y;
            acc[2][2] += a2 * w.z; acc[2][3] += a2 * w.w;
            acc[3][0] += a3 * w.x; acc[3][1] += a3 * w.y;
            acc[3][2] += a3 * w.z; acc[3][3] += a3 * w.w;
        }
        __syncthreads();
    }

    float4 b4 = *(const float4*)&bias[tx * 4];
#pragma unroll
    for (int mi = 0; mi < 4; mi++) {
        int row = m0 + ty * 4 + mi;
        if (row >= M) continue;
        float o[4];
        o[0] = acc[mi][0] + b4.x; o[1] = acc[mi][1] + b4.y;
        o[2] = acc[mi][2] + b4.z; o[3] = acc[mi][3] + b4.w;
        if (SILU) {
#pragma unroll
            for (int j = 0; j < 4; j++) o[j] = o[j] / (1.0f + expf(-o[j]));
        }
        if (HALF_OUT) {
            __half* C = (__half*)Cout;
#pragma unroll
            for (int j = 0; j < 4; j++) {
                int c = tx * 4 + j;
                int i = c & 63, g = c >> 6;
                __half hv = __float2half(o[j]);
                C[((size_t)row * 64 + i) * 8 + g] = hv;
                if (row > 0)
                    C[((size_t)(row - 1) * 64 + i) * 8 + 4 + g] = hv;
            }
        } else {
            float* C = (float*)Cout;
            *(float4*)&C[(size_t)row * 256 + tx * 4] =
                make_float4(o[0], o[1], o[2], o[3]);
        }
    }
}

// ---------------------------------------------------------------------------
// fp16 m16n8k16 fused 3-layer actv MLP, BM=128, 512 threads (16 warps,
// 4x4 grid of 32x64 warp tiles), 1 CTA/SM. Halves per-chip weight restaging
// vs BM=64 while keeping 16 warps/SM for latency hiding.
#define MLP_NT 512

__device__ __forceinline__ void do_layer_h(
    const float* __restrict__ Wg, int K,
    __half* sA, __half* sW,
    int tid, int wm, int wn, int gid, int tig,
    float acc[2][8][4])
{
#pragma unroll
    for (int mi = 0; mi < 2; mi++)
#pragma unroll
        for (int ni = 0; ni < 8; ni++)
#pragma unroll
            for (int c = 0; c < 4; c++) acc[mi][ni][c] = 0.0f;

    const unsigned short* sWu = (const unsigned short*)sW;
    const int nch = K >> 5;
    for (int ch = 0; ch < nch; ch++) {
        // stage W chunk [32 x 256] fp32 -> half rows
        const float4* W4 = (const float4*)(Wg + (size_t)ch * 32 * 256);
#pragma unroll
        for (int t = tid; t < 2048; t += MLP_NT) {
            int r = t >> 6, q = t & 63;
            float4 v = W4[r * 64 + q];
            uint32_t p0 = pack_half2(v.x, v.y);
            uint32_t p1 = pack_half2(v.z, v.w);
            *(uint2*)&sW[r * HAST + q * 4] = make_uint2(p0, p1);
        }
        __syncthreads();

#pragma unroll
        for (int ks = 0; ks < 2; ks++) {
            const int k0 = ch * 32 + ks * 16;  // sA col base
            const int kw = ks * 16;            // sW row base
            uint32_t a[2][4], b[8][2];
#pragma unroll
            for (int mi = 0; mi < 2; mi++) {
                int row = wm + mi * 16 + gid;
                a[mi][0] = *(const uint32_t*)&sA[row * HAST + k0 + 2 * tig];
                a[mi][1] = *(const uint32_t*)&sA[(row + 8) * HAST + k0 + 2 * tig];
                a[mi][2] = *(const uint32_t*)&sA[row * HAST + k0 + 2 * tig + 8];
                a[mi][3] = *(const uint32_t*)&sA[(row + 8) * HAST + k0 + 2 * tig + 8];
            }
#pragma unroll
            for (int ni = 0; ni < 8; ni++) {
                int n = wn + ni * 8 + gid;
                uint32_t lo0 = sWu[(kw + 2 * tig) * HAST + n];
                uint32_t hi0 = sWu[(kw + 2 * tig + 1) * HAST + n];
                uint32_t lo1 = sWu[(kw + 2 * tig + 8) * HAST + n];
                uint32_t hi1 = sWu[(kw + 2 * tig + 9) * HAST + n];
                b[ni][0] = lo0 | (hi0 << 16);
                b[ni][1] = lo1 | (hi1 << 16);
            }
#pragma unroll
            for (int mi = 0; mi < 2; mi++)
#pragma unroll
                for (int ni = 0; ni < 8; ni++)
                    asm volatile(
                        "mma.sync.aligned.m16n8k16.row.col.f32.f16.f16.f32 "
                        "{%0,%1,%2,%3}, {%4,%5,%6,%7}, {%8,%9}, {%0,%1,%2,%3};"
                        : "+f"(acc[mi][ni][0]), "+f"(acc[mi][ni][1]),
                          "+f"(acc[mi][ni][2]), "+f"(acc[mi][ni][3])
                        : "r"(a[mi][0]), "r"(a[mi][1]), "r"(a[mi][2]), "r"(a[mi][3]),
                          "r"(b[ni][0]), "r"(b[ni][1]));
        }
        __syncthreads();
    }
}

__global__ void __launch_bounds__(MLP_NT, 1) fused_mlp_actv(
    const float* __restrict__ in,
    const float* __restrict__ W1, const float* __restrict__ b1,
    const float* __restrict__ W2, const float* __restrict__ b2,
    const float* __restrict__ W3, const float* __restrict__ b3,
    __half* __restrict__ axH, int M)
{
    extern __shared__ char smraw[];
    __half* sA  = (__half*)smraw;                       // 128*HAST halfs
    __half* sW  = sA + 128 * HAST;                      // 32*HAST halfs
    float*  sb1 = (float*)(sW + 32 * HAST);
    float*  sb2 = sb1 + 256;
    float*  sb3 = sb2 + 256;

    const int tid = threadIdx.x;
    const int lane = tid & 31;
    const int w = tid >> 5;                 // 0..15
    const int gid = lane >> 2, tig = lane & 3;
    const int wm = (w >> 2) * 32;           // 0,32,64,96
    const int wn = (w & 3) * 64;            // 0,64,128,192
    const int m0 = blockIdx.x * 128;

    if (tid < 256) { sb1[tid] = b1[tid]; sb2[tid] = b2[tid]; sb3[tid] = b3[tid]; }

    // stage input rows (128 x 64 fp32 -> half): 4 threads/row, 16 halfs each
    {
        int r = tid >> 2;                   // 0..127
        int cb = (tid & 3) * 16;
        int row = m0 + r;
        __half* ar = &sA[r * HAST + cb];
#pragma unroll
        for (int q = 0; q < 4; q++) {
            float4 v = (row < M)
                ? *(const float4*)&in[(size_t)row * 64 + cb + q * 4]
                : make_float4(0.f, 0.f, 0.f, 0.f);
            *(uint2*)&ar[q * 4] = make_uint2(pack_half2(v.x, v.y),
                                             pack_half2(v.z, v.w));
        }
    }
    __syncthreads();

    float acc[2][8][4];

    do_layer_h(W1, 64, sA, sW, tid, wm, wn, gid, tig, acc);
#pragma unroll
    for (int mi = 0; mi < 2; mi++) {
        int r0 = wm + mi * 16 + gid;
#pragma unroll
        for (int ni = 0; ni < 8; ni++) {
            int c0 = wn + ni * 8 + 2 * tig;
            float bb0 = sb1[c0], bb1 = sb1[c0 + 1];
            *(uint32_t*)&sA[r0 * HAST + c0] =
                pack_half2(silu_fast(acc[mi][ni][0] + bb0),
                           silu_fast(acc[mi][ni][1] + bb1));
            *(uint32_t*)&sA[(r0 + 8) * HAST + c0] =
                pack_half2(silu_fast(acc[mi][ni][2] + bb0),
                           silu_fast(acc[mi][ni][3] + bb1));
        }
    }
    __syncthreads();

    do_layer_h(W2, 256, sA, sW, tid, wm, wn, gid, tig, acc);
#pragma unroll
    for (int mi = 0; mi < 2; mi++) {
        int r0 = wm + mi * 16 + gid;
#pragma unroll
        for (int ni = 0; ni < 8; ni++) {
            int c0 = wn + ni * 8 + 2 * tig;
            float bb0 = sb2[c0], bb1 = sb2[c0 + 1];
            *(uint32_t*)&sA[r0 * HAST + c0] =
                pack_half2(silu_fast(acc[mi][ni][0] + bb0),
                           silu_fast(acc[mi][ni][1] + bb1));
            *(uint32_t*)&sA[(r0 + 8) * HAST + c0] =
                pack_half2(silu_fast(acc[mi][ni][2] + bb0),
                           silu_fast(acc[mi][ni][3] + bb1));
        }
    }
    __syncthreads();

    do_layer_h(W3, 256, sA, sW, tid, wm, wn, gid, tig, acc);
#pragma unroll
    for (int mi = 0; mi < 2; mi++) {
        int r0 = wm + mi * 16 + gid;
#pragma unroll
        for (int ni = 0; ni < 8; ni++) {
            int c0 = wn + ni * 8 + 2 * tig;
            float bb0 = sb3[c0], bb1 = sb3[c0 + 1];
#pragma unroll
            for (int half = 0; half < 2; half++) {
                int row = m0 + r0 + half * 8;
                if (row >= M) continue;
                float v0 = acc[mi][ni][half * 2 + 0] + bb0;
                float v1 = acc[mi][ni][half * 2 + 1] + bb1;
                axH[((size_t)row * 64 + (c0 & 63)) * 8 + (c0 >> 6)] = __float2half(v0);
                axH[((size_t)row * 64 + ((c0 + 1) & 63)) * 8 + ((c0 + 1) >> 6)] = __float2half(v1);
            }
        }
    }
}

// ---------------------------------------------------------------------------
// atomic-free epilogue: 256 threads per src atom (4 quarters x 64 channels).
__global__ void __launch_bounds__(256) epilogue_quad(
    const __half* __restrict__ tblP,   // [TBL][64][8]
    const __half* __restrict__ axH,    // [B*A][64][8]
    const float4* __restrict__ erec,   // [E] sorted {rx,ry,rz,dst}
    const int* __restrict__ offs,      // [A+1]
    float* __restrict__ out_a, float* __restrict__ out_v,
    int A)
{
    __shared__ float red[4][64][17];

    const int a = blockIdx.x;
    const int q = threadIdx.x >> 6;
    const int i = threadIdx.x & 63;

    const int p0 = offs[a], p1 = offs[a + 1];

    float accx[B_DIM], accy[B_DIM], accz[B_DIM], acca[B_DIM];
#pragma unroll
    for (int b = 0; b < B_DIM; b++) {
        accx[b] = 0.f; accy[b] = 0.f; accz[b] = 0.f; acca[b] = 0.f;
    }

    int p = p0 + q;
    float4 rec = make_float4(0.f, 0.f, 0.f, 0.f);
    if (p < p1) rec = __ldg(&erec[p]);

    for (; p < p1; p += 4) {
        float4 rec_n = make_float4(0.f, 0.f, 0.f, 0.f);
        if (p + 4 < p1) rec_n = __ldg(&erec[p + 4]);

        float rx = rec.x, ry = rec.y, rz = rec.z;
        int ad = __float_as_int(rec.w);

        float r2 = rx * rx + ry * ry + rz * rz;
        float d  = sqrtf(r2);
        float inv = rsqrtf(0.1f + r2);
        float dx = rx * inv, dy = ry * inv, dz = rz * inv;

        float u = fminf(d * INV_STEP, (float)(TBL - 1) - 0.001f);
        int   i0 = (int)u;
        float fr = u - (float)i0;

        uint4 tp = *(const uint4*)(tblP + ((size_t)i0 * 64 + i) * 8);
        float2 c01 = __half22float2(*(__half2*)&tp.x);
        float2 c23 = __half22float2(*(__half2*)&tp.y);
        float2 n01 = __half22float2(*(__half2*)&tp.z);
        float2 n23 = __half22float2(*(__half2*)&tp.w);
        float d0 = c01.x + fr * (n01.x - c01.x);
        float d1 = c01.y + fr * (n01.y - c01.y);
        float d2 = c23.x + fr * (n23.x - c23.x);
        float d3 = c23.y + fr * (n23.y - c23.y);

#pragma unroll
        for (int b = 0; b < B_DIM; b++) {
            uint4 pk = *(const uint4*)(axH + (((size_t)b * A + ad) * 64 + i) * 8);
            float2 a01 = __half22float2(*(__half2*)&pk.x);
            float2 a23 = __half22float2(*(__half2*)&pk.y);
            float2 vxy = __half22float2(*(__half2*)&pk.z);
            float2 vzp = __half22float2(*(__half2*)&pk.w);
            float q0 = d0 * a01.x;
            float q1 = d1 * a01.y;
            float q2 = d2 * a23.x;
            float q3 = d3 * a23.y;
            float vx = vxy.x, vy = vxy.y, vz = vzp.x;

            float cx = vy * dz - vz * dy;
            float cy = vz * dx - vx * dz;
            float cz = vx * dy - vy * dx;

            accx[b] += vx * q0 + cx * q1 + dx * q2;
            accy[b] += vy * q0 + cy * q1 + dy * q2;
            accz[b] += vz * q0 + cz * q1 + dz * q2;
            acca[b] += q3;
        }

        rec = rec_n;
    }

#pragma unroll
    for (int b = 0; b < B_DIM; b++) {
        red[q][i][b * 4 + 0] = accx[b];
        red[q][i][b * 4 + 1] = accy[b];
        red[q][i][b * 4 + 2] = accz[b];
        red[q][i][b * 4 + 3] = acca[b];
    }
    __syncthreads();

    {
        int b = q;
        float sx = red[0][i][b * 4 + 0] + red[1][i][b * 4 + 0]
                 + red[2][i][b * 4 + 0] + red[3][i][b * 4 + 0];
        float sy = red[0][i][b * 4 + 1] + red[1][i][b * 4 + 1]
                 + red[2][i][b * 4 + 1] + red[3][i][b * 4 + 1];
        float sz = red[0][i][b * 4 + 2] + red[1][i][b * 4 + 2]
                 + red[2][i][b * 4 + 2] + red[3][i][b * 4 + 2];
        float sa = red[0][i][b * 4 + 3] + red[1][i][b * 4 + 3]
                 + red[2][i][b * 4 + 3] + red[3][i][b * 4 + 3];
        size_t ob = (((size_t)b * A + a) * 64 + i) * 3;
        out_v[ob + 0] = sx;
        out_v[ob + 1] = sy;
        out_v[ob + 2] = sz;
        out_a[((size_t)b * A + a) * 64 + i] = sa;
    }
}

// ---------------------------------------------------------------------------
#define SMEM_MLP ((128 * HAST + 32 * HAST) * 2 + 3 * 256 * 4)

extern "C" void kernel_launch(void* const* d_in, const int* in_sizes, int n_in,
                              void* d_out, int out_size) {
    const float* x_a  = (const float*)d_in[0];
    const float* x_v  = (const float*)d_in[1];
    const float* r_ij = (const float*)d_in[2];
    const int*   src  = (const int*)d_in[3];
    const int*   dst  = (const int*)d_in[4];
    const float* dW1 = (const float*)d_in[5];
    const float* db1 = (const float*)d_in[6];
    const float* dW2 = (const float*)d_in[7];
    const float* db2 = (const float*)d_in[8];
    const float* dW3 = (const float*)d_in[9];
    const float* db3 = (const float*)d_in[10];
    const float* aW1 = (const float*)d_in[11];
    const float* ab1 = (const float*)d_in[12];
    const float* aW2 = (const float*)d_in[13];
    const float* ab2 = (const float*)d_in[14];
    const float* aW3 = (const float*)d_in[15];
    const float* ab3 = (const float*)d_in[16];

    const int E  = in_sizes[3];
    const int BA = in_sizes[0] / NCH;
    const int A  = BA / B_DIM;

    float *enc, *tmpA, *tmpB;
    float4* erec;
    __half *axH, *tblP;
    int *hist, *offs, *cursor;
    cudaGetSymbolAddress((void**)&axH,    g_axH);
    cudaGetSymbolAddress((void**)&tblP,   g_tblP);
    cudaGetSymbolAddress((void**)&enc,    g_enc);
    cudaGetSymbolAddress((void**)&tmpA,   g_tmpA);
    cudaGetSymbolAddress((void**)&tmpB,   g_tmpB);
    cudaGetSymbolAddress((void**)&erec,   g_erec);
    cudaGetSymbolAddress((void**)&hist,   g_hist);
    cudaGetSymbolAddress((void**)&offs,   g_offs);
    cudaGetSymbolAddress((void**)&cursor, g_cursor);

    // One-time resource setup (first call happens before the harness's
    // pre-capture memory baseline; capture call creates nothing).
    static cudaStream_t s1 = nullptr, s2 = nullptr;
    static cudaEvent_t evRoot = nullptr, ev1 = nullptr, ev2 = nullptr;
    if (s1 == nullptr) {
        cudaStreamCreateWithFlags(&s1, cudaStreamNonBlocking);
        cudaStreamCreateWithFlags(&s2, cudaStreamNonBlocking);
        cudaEventCreateWithFlags(&evRoot, cudaEventDisableTiming);
        cudaEventCreateWithFlags(&ev1, cudaEventDisableTiming);
        cudaEventCreateWithFlags(&ev2, cudaEventDisableTiming);
        cudaFuncSetAttribute(fused_mlp_actv,
            cudaFuncAttributeMaxDynamicSharedMemorySize, SMEM_MLP);
    }

    float* out_a = (float*)d_out;
    float* out_v = out_a + (size_t)BA * NCH;

    // Fork side streams off the origin stream (capture-legal: events only).
    cudaEventRecord(evRoot, 0);
    cudaStreamWaitEvent(s1, evRoot, 0);
    cudaStreamWaitEvent(s2, evRoot, 0);

    // ---- stream 0 (origin): counting sort chain + xv convert ----
    convert_xv<<<(BA * NCH + 255) / 256, 256>>>(x_v, axH, BA * NCH);
    zero_hist<<<(A + 255) / 256, 256>>>(hist, A);
    hist_kernel<<<(E + 255) / 256, 256>>>(src, hist, E);
    scan_kernel<<<1, 1024>>>(hist, offs, cursor, A);
    scatter_kernel<<<(E + 255) / 256, 256>>>(src, dst, r_ij, cursor, erec, E);

    // ---- stream 1: actv MLP (fp16 tensor cores, BM=128/512thr) ----
    fused_mlp_actv<<<(BA + 127) / 128, MLP_NT, SMEM_MLP, s1>>>(
        x_a, aW1, ab1, aW2, ab2, aW3, ab3, axH, BA);

    // ---- stream 2: dist-table build (FFMA pipe) ----
    encode_table<<<(TBL * 64 + 255) / 256, 256, 0, s2>>>(enc);
    mlp_small<64,  true,  false><<<TBL / 16, 256, 0, s2>>>(enc,  dW1, db1, tmpA, TBL);
    mlp_small<256, true,  false><<<TBL / 16, 256, 0, s2>>>(tmpA, dW2, db2, tmpB, TBL);
    mlp_small<256, false, true ><<<TBL / 16, 256, 0, s2>>>(tmpB, dW3, db3, tblP, TBL);

    // ---- join ----
    cudaEventRecord(ev1, s1);
    cudaEventRecord(ev2, s2);
    cudaStreamWaitEvent(0, ev1, 0);
    cudaStreamWaitEvent(0, ev2, 0);

    // ---- epilogue on origin stream ----
    epilogue_quad<<<A, 256>>>(tblP, axH, erec, offs, out_a, out_v, A);
}

// round 15
// speedup vs baseline: 1.0468x; 1.0468x over previous
#include <cuda_runtime.h>
#include <cuda_fp16.h>
#include <math.h>
#include <stdint.h>

// Problem constants
#define E_MAX   320000
#define A_MAX   10000
#define B_DIM   4
#define NCH     64
#define HID     256
#define HAST    264   // half-element smem row stride (even, 8-half aligned)

// dist-MLP lookup table
#define TBL     1024
#define D_MAX   8.0f
#define DSTEP   (D_MAX / (float)TBL)
#define INV_STEP ((float)TBL / D_MAX)

// Scratch (static __device__; allocation APIs forbidden)
__device__ __align__(16) __half g_axH [B_DIM * A_MAX * NCH * 8];
__device__ __align__(16) __half g_tblP[TBL * NCH * 8];
__device__ __align__(16) float  g_enc [TBL * NCH];
__device__ __align__(16) float  g_tmpA[TBL * HID];
__device__ __align__(16) float  g_tmpB[TBL * HID];
__device__ __align__(16) float4 g_erec[E_MAX];   // sorted edge records {rx,ry,rz,dst}
__device__ int g_hist  [A_MAX];
__device__ int g_offs  [A_MAX + 1];
__device__ int g_cursor[A_MAX];

// ---------------------------------------------------------------------------
__device__ __forceinline__ float silu_fast(float v) {
    return v / (1.0f + __expf(-v));
}
__device__ __forceinline__ uint32_t pack_half2(float lo, float hi) {
    __half2 h = __floats2half2_rn(lo, hi);
    return *(uint32_t*)&h;
}

// ---------------------------------------------------------------------------
__global__ void zero_hist(int* __restrict__ hist, int A) {
    int t = blockIdx.x * blockDim.x + threadIdx.x;
    if (t < A) hist[t] = 0;
}

__global__ void convert_xv(const float* __restrict__ x_v, __half* __restrict__ axH,
                           int n) {
    int t = blockIdx.x * blockDim.x + threadIdx.x;
    if (t >= n) return;
    float vx = x_v[3 * t + 0];
    float vy = x_v[3 * t + 1];
    float vz = x_v[3 * t + 2];
    __half2* dp = (__half2*)(axH + (size_t)t * 8 + 4);
    dp[0] = __floats2half2_rn(vx, vy);
    dp[1] = __floats2half2_rn(vz, 0.0f);
}

__global__ void encode_table(float* __restrict__ enc) {
    int t = blockIdx.x * blockDim.x + threadIdx.x;
    if (t >= TBL * 64) return;
    int idx = t >> 6, j = t & 63;
    float d = (float)idx * DSTEP;
    int jj = (j < 32) ? j : (j - 32);
    float c = 0.31415926535897932f * (float)(1 + (jj >> 1));
    float ph = c * d;
    enc[t] = (j < 32) ? cosf(ph) : sinf(ph);
}

// ---------------------------------------------------------------------------
__global__ void hist_kernel(const int* __restrict__ src, int* __restrict__ hist, int E) {
    int e = blockIdx.x * blockDim.x + threadIdx.x;
    if (e < E) atomicAdd(&hist[src[e]], 1);
}

// shfl-based block scan, 1024 threads, chunked over A
__global__ void scan_kernel(const int* __restrict__ hist, int* __restrict__ offs,
                            int* __restrict__ cursor, int A) {
    __shared__ int wsum[32];
    __shared__ int carry_s;
    int tid = threadIdx.x, lane = tid & 31, wid = tid >> 5;
    if (tid == 0) { carry_s = 0; offs[0] = 0; }
    __syncthreads();
    for (int base = 0; base < A; base += 1024) {
        int i = base + tid;
        int v = (i < A) ? hist[i] : 0;
        int x = v;
#pragma unroll
        for (int d = 1; d < 32; d <<= 1) {
            int t = __shfl_up_sync(0xFFFFFFFFu, x, d);
            if (lane >= d) x += t;
        }
        if (lane == 31) wsum[wid] = x;
        __syncthreads();
        if (wid == 0) {
            int s = wsum[lane];
#pragma unroll
            for (int d = 1; d < 32; d <<= 1) {
                int t = __shfl_up_sync(0xFFFFFFFFu, s, d);
                if (lane >= d) s += t;
            }
            wsum[lane] = s;
        }
        __syncthreads();
        int woff = (wid > 0) ? wsum[wid - 1] : 0;
        int inc = carry_s + woff + x;
        if (i < A) { offs[i + 1] = inc; cursor[i] = inc - v; }
        __syncthreads();
        if (tid == 1023) carry_s = inc;
        __syncthreads();
    }
}

// scatter sorted edge records {rx, ry, rz, dst-as-float-bits}
__global__ void scatter_kernel(const int* __restrict__ src,
                               const int* __restrict__ dst,
                               const float* __restrict__ r_ij,
                               int* __restrict__ cursor,
                               float4* __restrict__ erec, int E) {
    int e = blockIdx.x * blockDim.x + threadIdx.x;
    if (e < E) {
        int p = atomicAdd(&cursor[src[e]], 1);
        float4 rec;
        rec.x = r_ij[3 * e + 0];
        rec.y = r_ij[3 * e + 1];
        rec.z = r_ij[3 * e + 2];
        rec.w = __int_as_float(dst[e]);
        erec[p] = rec;
    }
}

// ---------------------------------------------------------------------------
// fp32 SIMT GEMM for the table build: BM=16, BN=256, BK=32.
template <int K, bool SILU, bool HALF_OUT>
__global__ void __launch_bounds__(256) mlp_small(
    const float* __restrict__ A, const float* __restrict__ W,
    const float* __restrict__ bias, void* __restrict__ Cout, int M)
{
    constexpr int BM = 16, BK = 32;
    __shared__ float As[BM][BK + 1];
    __shared__ float Ws[BK][256];

    const int m0 = blockIdx.x * BM;
    const int tid = threadIdx.x;
    const int tx = tid & 63;
    const int ty = tid >> 6;

    float acc[4][4];
#pragma unroll
    for (int i = 0; i < 4; i++)
#pragma unroll
        for (int j = 0; j < 4; j++) acc[i][j] = 0.0f;

    for (int k0 = 0; k0 < K; k0 += BK) {
        {
            int r = tid >> 4, c2 = (tid & 15) * 2;
            int row = m0 + r;
            float2 v = (row < M) ? *(const float2*)&A[(size_t)row * K + k0 + c2]
                                 : make_float2(0.f, 0.f);
            As[r][c2] = v.x; As[r][c2 + 1] = v.y;
        }
#pragma unroll
        for (int s = 0; s < 8; s++) {
            int f4 = s * 256 + tid;
            int r = f4 >> 6, c4 = f4 & 63;
            float4 w = *(const float4*)&W[(size_t)(k0 + r) * 256 + c4 * 4];
            *(float4*)&Ws[r][c4 * 4] = w;
        }
        __syncthreads();

#pragma unroll
        for (int kk = 0; kk < BK; kk++) {
            float4 w = *(const float4*)&Ws[kk][tx * 4];
            float a0 = As[ty * 4 + 0][kk];
            float a1 = As[ty * 4 + 1][kk];
            float a2 = As[ty * 4 + 2][kk];
            float a3 = As[ty * 4 + 3][kk];
            acc[0][0] += a0 * w.x; acc[0][1] += a0 * w.y;
            acc[0][2] += a0 * w.z; acc[0][3] += a0 * w.w;
            acc[1][0] += a1 * w.x; acc[1][1] += a1 * w.y;
            acc[1][2] += a1 * w.z; acc[1][3] += a1 * w.w;
            acc[2][0] += a2 * w.x; acc[2][1] += a2 * w.y;
            acc[2][2] += a2 * w.z; acc[2][3] += a2 * w.w;
            acc[3][0] += a3 * w.x; acc[3][1] += a3 * w.y;
            acc[3][2] += a3 * w.z; acc[3][3] += a3 * w.w;
        }
        __syncthreads();
    }

    float4 b4 = *(const float4*)&bias[tx * 4];
#pragma unroll
    for (int mi = 0; mi < 4; mi++) {
        int row = m0 + ty * 4 + mi;
        if (row >= M) continue;
        float o[4];
        o[0] = acc[mi][0] + b4.x; o[1] = acc[mi][1] + b4.y;
        o[2] = acc[mi][2] + b4.z; o[3] = acc[mi][3] + b4.w;
        if (SILU) {
#pragma unroll
            for (int j = 0; j < 4; j++) o[j] = o[j] / (1.0f + expf(-o[j]));
        }
        if (HALF_OUT) {
            __half* C = (__half*)Cout;
#pragma unroll
            for (int j = 0; j < 4; j++) {
                int c = tx * 4 + j;
                int i = c & 63, g = c >> 6;
                __half hv = __float2half(o[j]);
                C[((size_t)row * 64 + i) * 8 + g] = hv;
                if (row > 0)
                    C[((size_t)(row - 1) * 64 + i) * 8 + 4 + g] = hv;
            }
        } else {
            float* C = (float*)Cout;
            *(float4*)&C[(size_t)row * 256 + tx * 4] =
                make_float4(o[0], o[1], o[2], o[3]);
        }
    }
}

// ---------------------------------------------------------------------------
// fp16 m16n8k16 fused 3-layer actv MLP, BM=64, 256 threads, 2 CTAs/SM
// (the proven R13 config) with DOUBLE-BUFFERED weight staging: stage chunk
// c+1 while MMA-ing chunk c; one __syncthreads per chunk instead of two.
__device__ __forceinline__ void stage_w_chunk(
    const float* __restrict__ Wg, int ch, __half* buf, int tid)
{
    const float4* W4 = (const float4*)(Wg + (size_t)ch * 32 * 256);
#pragma unroll
    for (int t = tid; t < 2048; t += 256) {
        int r = t >> 6, q = t & 63;
        float4 v = W4[r * 64 + q];
        *(uint2*)&buf[r * HAST + q * 4] =
            make_uint2(pack_half2(v.x, v.y), pack_half2(v.z, v.w));
    }
}

__device__ __forceinline__ void do_layer_h(
    const float* __restrict__ Wg, int K,
    __half* sA, __half* sW,      // sW: two buffers of 32*HAST halfs
    int tid, int wm, int wn, int gid, int tig,
    float acc[2][8][4])
{
#pragma unroll
    for (int mi = 0; mi < 2; mi++)
#pragma unroll
        for (int ni = 0; ni < 8; ni++)
#pragma unroll
            for (int c = 0; c < 4; c++) acc[mi][ni][c] = 0.0f;

    const int nch = K >> 5;
    stage_w_chunk(Wg, 0, sW, tid);
    __syncthreads();

    for (int ch = 0; ch < nch; ch++) {
        __half* cur = sW + (ch & 1) * 32 * HAST;
        if (ch + 1 < nch)
            stage_w_chunk(Wg, ch + 1, sW + ((ch + 1) & 1) * 32 * HAST, tid);

        const unsigned short* sWu = (const unsigned short*)cur;
#pragma unroll
        for (int ks = 0; ks < 2; ks++) {
            const int k0 = ch * 32 + ks * 16;  // sA col base
            const int kw = ks * 16;            // cur row base
            uint32_t a[2][4], b[8][2];
#pragma unroll
            for (int mi = 0; mi < 2; mi++) {
                int row = wm + mi * 16 + gid;
                a[mi][0] = *(const uint32_t*)&sA[row * HAST + k0 + 2 * tig];
                a[mi][1] = *(const uint32_t*)&sA[(row + 8) * HAST + k0 + 2 * tig];
                a[mi][2] = *(const uint32_t*)&sA[row * HAST + k0 + 2 * tig + 8];
                a[mi][3] = *(const uint32_t*)&sA[(row + 8) * HAST + k0 + 2 * tig + 8];
            }
#pragma unroll
            for (int ni = 0; ni < 8; ni++) {
                int n = wn + ni * 8 + gid;
                uint32_t lo0 = sWu[(kw + 2 * tig) * HAST + n];
                uint32_t hi0 = sWu[(kw + 2 * tig + 1) * HAST + n];
                uint32_t lo1 = sWu[(kw + 2 * tig + 8) * HAST + n];
                uint32_t hi1 = sWu[(kw + 2 * tig + 9) * HAST + n];
                b[ni][0] = lo0 | (hi0 << 16);
                b[ni][1] = lo1 | (hi1 << 16);
            }
#pragma unroll
            for (int mi = 0; mi < 2; mi++)
#pragma unroll
                for (int ni = 0; ni < 8; ni++)
                    asm volatile(
                        "mma.sync.aligned.m16n8k16.row.col.f32.f16.f16.f32 "
                        "{%0,%1,%2,%3}, {%4,%5,%6,%7}, {%8,%9}, {%0,%1,%2,%3};"
                        : "+f"(acc[mi][ni][0]), "+f"(acc[mi][ni][1]),
                          "+f"(acc[mi][ni][2]), "+f"(acc[mi][ni][3])
                        : "r"(a[mi][0]), "r"(a[mi][1]), "r"(a[mi][2]), "r"(a[mi][3]),
                          "r"(b[ni][0]), "r"(b[ni][1]));
        }
        __syncthreads();  // staging of ch+1 done AND mma reads of cur done
    }
}

__global__ void __launch_bounds__(256, 2) fused_mlp_actv(
    const float* __restrict__ in,
    const float* __restrict__ W1, const float* __restrict__ b1,
    const float* __restrict__ W2, const float* __restrict__ b2,
    const float* __restrict__ W3, const float* __restrict__ b3,
    __half* __restrict__ axH, int M)
{
    extern __shared__ char smraw[];
    __half* sA  = (__half*)smraw;                       // 64*HAST halfs
    __half* sW  = sA + 64 * HAST;                       // 2 x 32*HAST halfs
    float*  sb1 = (float*)(sW + 64 * HAST);
    float*  sb2 = sb1 + 256;
    float*  sb3 = sb2 + 256;

    const int tid = threadIdx.x;
    const int lane = tid & 31;
    const int w = tid >> 5;
    const int gid = lane >> 2, tig = lane & 3;
    const int wm = (w >> 2) * 32, wn = (w & 3) * 64;
    const int m0 = blockIdx.x * 64;

    sb1[tid] = b1[tid]; sb2[tid] = b2[tid]; sb3[tid] = b3[tid];

    // stage input rows (64 x 64 fp32 -> half): 4 threads/row, 16 halfs each
    {
        int r = tid >> 2;
        int cb = (tid & 3) * 16;
        int row = m0 + r;
        __half* ar = &sA[r * HAST + cb];
#pragma unroll
        for (int q = 0; q < 4; q++) {
            float4 v = (row < M)
                ? *(const float4*)&in[(size_t)row * 64 + cb + q * 4]
                : make_float4(0.f, 0.f, 0.f, 0.f);
            *(uint2*)&ar[q * 4] = make_uint2(pack_half2(v.x, v.y),
                                             pack_half2(v.z, v.w));
        }
    }
    __syncthreads();

    float acc[2][8][4];

    do_layer_h(W1, 64, sA, sW, tid, wm, wn, gid, tig, acc);
#pragma unroll
    for (int mi = 0; mi < 2; mi++) {
        int r0 = wm + mi * 16 + gid;
#pragma unroll
        for (int ni = 0; ni < 8; ni++) {
            int c0 = wn + ni * 8 + 2 * tig;
            float bb0 = sb1[c0], bb1 = sb1[c0 + 1];
            *(uint32_t*)&sA[r0 * HAST + c0] =
                pack_half2(silu_fast(acc[mi][ni][0] + bb0),
                           silu_fast(acc[mi][ni][1] + bb1));
            *(uint32_t*)&sA[(r0 + 8) * HAST + c0] =
                pack_half2(silu_fast(acc[mi][ni][2] + bb0),
                           silu_fast(acc[mi][ni][3] + bb1));
        }
    }
    __syncthreads();

    do_layer_h(W2, 256, sA, sW, tid, wm, wn, gid, tig, acc);
#pragma unroll
    for (int mi = 0; mi < 2; mi++) {
        int r0 = wm + mi * 16 + gid;
#pragma unroll
        for (int ni = 0; ni < 8; ni++) {
            int c0 = wn + ni * 8 + 2 * tig;
            float bb0 = sb2[c0], bb1 = sb2[c0 + 1];
            *(uint32_t*)&sA[r0 * HAST + c0] =
                pack_half2(silu_fast(acc[mi][ni][0] + bb0),
                           silu_fast(acc[mi][ni][1] + bb1));
            *(uint32_t*)&sA[(r0 + 8) * HAST + c0] =
                pack_half2(silu_fast(acc[mi][ni][2] + bb0),
                           silu_fast(acc[mi][ni][3] + bb1));
        }
    }
    __syncthreads();

    do_layer_h(W3, 256, sA, sW, tid, wm, wn, gid, tig, acc);
#pragma unroll
    for (int mi = 0; mi < 2; mi++) {
        int r0 = wm + mi * 16 + gid;
#pragma unroll
        for (int ni = 0; ni < 8; ni++) {
            int c0 = wn + ni * 8 + 2 * tig;
            float bb0 = sb3[c0], bb1 = sb3[c0 + 1];
#pragma unroll
            for (int half = 0; half < 2; half++) {
                int row = m0 + r0 + half * 8;
                if (row >= M) continue;
                float v0 = acc[mi][ni][half * 2 + 0] + bb0;
                float v1 = acc[mi][ni][half * 2 + 1] + bb1;
                axH[((size_t)row * 64 + (c0 & 63)) * 8 + (c0 >> 6)] = __float2half(v0);
                axH[((size_t)row * 64 + ((c0 + 1) & 63)) * 8 + ((c0 + 1) >> 6)] = __float2half(v1);
            }
        }
    }
}

// ---------------------------------------------------------------------------
// atomic-free epilogue: 256 threads per src atom (4 quarters x 64 channels).
__global__ void __launch_bounds__(256) epilogue_quad(
    const __half* __restrict__ tblP,   // [TBL][64][8]
    const __half* __restrict__ axH,    // [B*A][64][8]
    const float4* __restrict__ erec,   // [E] sorted {rx,ry,rz,dst}
    const int* __restrict__ offs,      // [A+1]
    float* __restrict__ out_a, float* __restrict__ out_v,
    int A)
{
    __shared__ float red[4][64][17];

    const int a = blockIdx.x;
    const int q = threadIdx.x >> 6;
    const int i = threadIdx.x & 63;

    const int p0 = offs[a], p1 = offs[a + 1];

    float accx[B_DIM], accy[B_DIM], accz[B_DIM], acca[B_DIM];
#pragma unroll
    for (int b = 0; b < B_DIM; b++) {
        accx[b] = 0.f; accy[b] = 0.f; accz[b] = 0.f; acca[b] = 0.f;
    }

    int p = p0 + q;
    float4 rec = make_float4(0.f, 0.f, 0.f, 0.f);
    if (p < p1) rec = __ldg(&erec[p]);

    for (; p < p1; p += 4) {
        float4 rec_n = make_float4(0.f, 0.f, 0.f, 0.f);
        if (p + 4 < p1) rec_n = __ldg(&erec[p + 4]);

        float rx = rec.x, ry = rec.y, rz = rec.z;
        int ad = __float_as_int(rec.w);

        float r2 = rx * rx + ry * ry + rz * rz;
        float d  = sqrtf(r2);
        float inv = rsqrtf(0.1f + r2);
        float dx = rx * inv, dy = ry * inv, dz = rz * inv;

        float u = fminf(d * INV_STEP, (float)(TBL - 1) - 0.001f);
        int   i0 = (int)u;
        float fr = u - (float)i0;

        uint4 tp = *(const uint4*)(tblP + ((size_t)i0 * 64 + i) * 8);
        float2 c01 = __half22float2(*(__half2*)&tp.x);
        float2 c23 = __half22float2(*(__half2*)&tp.y);
        float2 n01 = __half22float2(*(__half2*)&tp.z);
        float2 n23 = __half22float2(*(__half2*)&tp.w);
        float d0 = c01.x + fr * (n01.x - c01.x);
        float d1 = c01.y + fr * (n01.y - c01.y);
        float d2 = c23.x + fr * (n23.x - c23.x);
        float d3 = c23.y + fr * (n23.y - c23.y);

#pragma unroll
        for (int b = 0; b < B_DIM; b++) {
            uint4 pk = *(const uint4*)(axH + (((size_t)b * A + ad) * 64 + i) * 8);
            float2 a01 = __half22float2(*(__half2*)&pk.x);
            float2 a23 = __half22float2(*(__half2*)&pk.y);
            float2 vxy = __half22float2(*(__half2*)&pk.z);
            float2 vzp = __half22float2(*(__half2*)&pk.w);
            float q0 = d0 * a01.x;
            float q1 = d1 * a01.y;
            float q2 = d2 * a23.x;
            float q3 = d3 * a23.y;
            float vx = vxy.x, vy = vxy.y, vz = vzp.x;

            float cx = vy * dz - vz * dy;
            float cy = vz * dx - vx * dz;
            float cz = vx * dy - vy * dx;

            accx[b] += vx * q0 + cx * q1 + dx * q2;
            accy[b] += vy * q0 + cy * q1 + dy * q2;
            accz[b] += vz * q0 + cz * q1 + dz * q2;
            acca[b] += q3;
        }

        rec = rec_n;
    }

#pragma unroll
    for (int b = 0; b < B_DIM; b++) {
        red[q][i][b * 4 + 0] = accx[b];
        red[q][i][b * 4 + 1] = accy[b];
        red[q][i][b * 4 + 2] = accz[b];
        red[q][i][b * 4 + 3] = acca[b];
    }
    __syncthreads();

    {
        int b = q;
        float sx = red[0][i][b * 4 + 0] + red[1][i][b * 4 + 0]
                 + red[2][i][b * 4 + 0] + red[3][i][b * 4 + 0];
        float sy = red[0][i][b * 4 + 1] + red[1][i][b * 4 + 1]
                 + red[2][i][b * 4 + 1] + red[3][i][b * 4 + 1];
        float sz = red[0][i][b * 4 + 2] + red[1][i][b * 4 + 2]
                 + red[2][i][b * 4 + 2] + red[3][i][b * 4 + 2];
        float sa = red[0][i][b * 4 + 3] + red[1][i][b * 4 + 3]
                 + red[2][i][b * 4 + 3] + red[3][i][b * 4 + 3];
        size_t ob = (((size_t)b * A + a) * 64 + i) * 3;
        out_v[ob + 0] = sx;
        out_v[ob + 1] = sy;
        out_v[ob + 2] = sz;
        out_a[((size_t)b * A + a) * 64 + i] = sa;
    }
}

// ---------------------------------------------------------------------------
#define SMEM_MLP ((64 * HAST + 64 * HAST) * 2 + 3 * 256 * 4)

extern "C" void kernel_launch(void* const* d_in, const int* in_sizes, int n_in,
                              void* d_out, int out_size) {
    const float* x_a  = (const float*)d_in[0];
    const float* x_v  = (const float*)d_in[1];
    const float* r_ij = (const float*)d_in[2];
    const int*   src  = (const int*)d_in[3];
    const int*   dst  = (const int*)d_in[4];
    const float* dW1 = (const float*)d_in[5];
    const float* db1 = (const float*)d_in[6];
    const float* dW2 = (const float*)d_in[7];
    const float* db2 = (const float*)d_in[8];
    const float* dW3 = (const float*)d_in[9];
    const float* db3 = (const float*)d_in[10];
    const float* aW1 = (const float*)d_in[11];
    const float* ab1 = (const float*)d_in[12];
    const float* aW2 = (const float*)d_in[13];
    const float* ab2 = (const float*)d_in[14];
    const float* aW3 = (const float*)d_in[15];
    const float* ab3 = (const float*)d_in[16];

    const int E  = in_sizes[3];
    const int BA = in_sizes[0] / NCH;
    const int A  = BA / B_DIM;

    float *enc, *tmpA, *tmpB;
    float4* erec;
    __half *axH, *tblP;
    int *hist, *offs, *cursor;
    cudaGetSymbolAddress((void**)&axH,    g_axH);
    cudaGetSymbolAddress((void**)&tblP,   g_tblP);
    cudaGetSymbolAddress((void**)&enc,    g_enc);
    cudaGetSymbolAddress((void**)&tmpA,   g_tmpA);
    cudaGetSymbolAddress((void**)&tmpB,   g_tmpB);
    cudaGetSymbolAddress((void**)&erec,   g_erec);
    cudaGetSymbolAddress((void**)&hist,   g_hist);
    cudaGetSymbolAddress((void**)&offs,   g_offs);
    cudaGetSymbolAddress((void**)&cursor, g_cursor);

    // One-time resource setup (first call happens before the harness's
    // pre-capture memory baseline; capture call creates nothing).
    static cudaStream_t s1 = nullptr, s2 = nullptr;
    static cudaEvent_t evRoot = nullptr, ev1 = nullptr, ev2 = nullptr;
    if (s1 == nullptr) {
        cudaStreamCreateWithFlags(&s1, cudaStreamNonBlocking);
        cudaStreamCreateWithFlags(&s2, cudaStreamNonBlocking);
        cudaEventCreateWithFlags(&evRoot, cudaEventDisableTiming);
        cudaEventCreateWithFlags(&ev1, cudaEventDisableTiming);
        cudaEventCreateWithFlags(&ev2, cudaEventDisableTiming);
        cudaFuncSetAttribute(fused_mlp_actv,
            cudaFuncAttributeMaxDynamicSharedMemorySize, SMEM_MLP);
    }

    float* out_a = (float*)d_out;
    float* out_v = out_a + (size_t)BA * NCH;

    // Fork side streams off the origin stream (capture-legal: events only).
    cudaEventRecord(evRoot, 0);
    cudaStreamWaitEvent(s1, evRoot, 0);
    cudaStreamWaitEvent(s2, evRoot, 0);

    // ---- stream 0 (origin): counting sort chain + xv convert ----
    convert_xv<<<(BA * NCH + 255) / 256, 256>>>(x_v, axH, BA * NCH);
    zero_hist<<<(A + 255) / 256, 256>>>(hist, A);
    hist_kernel<<<(E + 255) / 256, 256>>>(src, hist, E);
    scan_kernel<<<1, 1024>>>(hist, offs, cursor, A);
    scatter_kernel<<<(E + 255) / 256, 256>>>(src, dst, r_ij, cursor, erec, E);

    // ---- stream 1: actv MLP (fp16 tensor cores, BM=64, 2 CTAs/SM) ----
    fused_mlp_actv<<<(BA + 63) / 64, 256, SMEM_MLP, s1>>>(
        x_a, aW1, ab1, aW2, ab2, aW3, ab3, axH, BA);

    // ---- stream 2: dist-table build (FFMA pipe) ----
    encode_table<<<(TBL * 64 + 255) / 256, 256, 0, s2>>>(enc);
    mlp_small<64,  true,  false><<<TBL / 16, 256, 0, s2>>>(enc,  dW1, db1, tmpA, TBL);
    mlp_small<256, true,  false><<<TBL / 16, 256, 0, s2>>>(tmpA, dW2, db2, tmpB, TBL);
    mlp_small<256, false, true ><<<TBL / 16, 256, 0, s2>>>(tmpB, dW3, db3, tblP, TBL);

    // ---- join ----
    cudaEventRecord(ev1, s1);
    cudaEventRecord(ev2, s2);
    cudaStreamWaitEvent(0, ev1, 0);
    cudaStreamWaitEvent(0, ev2, 0);

    // ---- epilogue on origin stream ----
    epilogue_quad<<<A, 256>>>(tblP, axH, erec, offs, out_a, out_v, A);
}

// round 16
// speedup vs baseline: 1.1057x; 1.0563x over previous
#include <cuda_runtime.h>
#include <cuda_fp16.h>
#include <math.h>
#include <stdint.h>

// Problem constants
#define E_MAX   320000
#define A_MAX   10000
#define B_DIM   4
#define NCH     64
#define HID     256
#define HAST    264   // half-element smem row stride (even, 8-half aligned)

// dist-MLP lookup table
#define TBL     1024
#define D_MAX   8.0f
#define DSTEP   (D_MAX / (float)TBL)
#define INV_STEP ((float)TBL / D_MAX)

// Scratch (static __device__; allocation APIs forbidden)
__device__ __align__(16) __half g_axH [B_DIM * A_MAX * NCH * 8];
__device__ __align__(16) __half g_tblP[TBL * NCH * 8];
__device__ __align__(16) float  g_enc [TBL * NCH];
__device__ __align__(16) float  g_tmpA[TBL * HID];
__device__ __align__(16) float  g_tmpB[TBL * HID];
__device__ __align__(16) float4 g_erec[E_MAX];   // sorted edge records {rx,ry,rz,dst}
__device__ __align__(16) __half g_w1H[NCH * HID];   // actv weights, fp16
__device__ __align__(16) __half g_w2H[HID * HID];
__device__ __align__(16) __half g_w3H[HID * HID];
__device__ int g_hist  [A_MAX];
__device__ int g_offs  [A_MAX + 1];
__device__ int g_cursor[A_MAX];

// ---------------------------------------------------------------------------
__device__ __forceinline__ float silu_fast(float v) {
    return v / (1.0f + __expf(-v));
}
__device__ __forceinline__ uint32_t pack_half2(float lo, float hi) {
    __half2 h = __floats2half2_rn(lo, hi);
    return *(uint32_t*)&h;
}

// ---------------------------------------------------------------------------
__global__ void zero_hist(int* __restrict__ hist, int A) {
    int t = blockIdx.x * blockDim.x + threadIdx.x;
    if (t < A) hist[t] = 0;
}

__global__ void convert_xv(const float* __restrict__ x_v, __half* __restrict__ axH,
                           int n) {
    int t = blockIdx.x * blockDim.x + threadIdx.x;
    if (t >= n) return;
    float vx = x_v[3 * t + 0];
    float vy = x_v[3 * t + 1];
    float vz = x_v[3 * t + 2];
    __half2* dp = (__half2*)(axH + (size_t)t * 8 + 4);
    dp[0] = __floats2half2_rn(vx, vy);
    dp[1] = __floats2half2_rn(vz, 0.0f);
}

// fp32 -> fp16 weight conversion (same rounding as the old in-loop convert)
__global__ void convert_w(const float* __restrict__ W, __half* __restrict__ WH,
                          int n2 /* = n/2 */) {
    int t = blockIdx.x * blockDim.x + threadIdx.x;
    if (t >= n2) return;
    float2 v = *(const float2*)&W[2 * t];
    ((__half2*)WH)[t] = __floats2half2_rn(v.x, v.y);
}

__global__ void encode_table(float* __restrict__ enc) {
    int t = blockIdx.x * blockDim.x + threadIdx.x;
    if (t >= TBL * 64) return;
    int idx = t >> 6, j = t & 63;
    float d = (float)idx * DSTEP;
    int jj = (j < 32) ? j : (j - 32);
    float c = 0.31415926535897932f * (float)(1 + (jj >> 1));
    float ph = c * d;
    enc[t] = (j < 32) ? cosf(ph) : sinf(ph);
}

// ---------------------------------------------------------------------------
__global__ void hist_kernel(const int* __restrict__ src, int* __restrict__ hist, int E) {
    int e = blockIdx.x * blockDim.x + threadIdx.x;
    if (e < E) atomicAdd(&hist[src[e]], 1);
}

// shfl-based block scan, 1024 threads, chunked over A
__global__ void scan_kernel(const int* __restrict__ hist, int* __restrict__ offs,
                            int* __restrict__ cursor, int A) {
    __shared__ int wsum[32];
    __shared__ int carry_s;
    int tid = threadIdx.x, lane = tid & 31, wid = tid >> 5;
    if (tid == 0) { carry_s = 0; offs[0] = 0; }
    __syncthreads();
    for (int base = 0; base < A; base += 1024) {
        int i = base + tid;
        int v = (i < A) ? hist[i] : 0;
        int x = v;
#pragma unroll
        for (int d = 1; d < 32; d <<= 1) {
            int t = __shfl_up_sync(0xFFFFFFFFu, x, d);
            if (lane >= d) x += t;
        }
        if (lane == 31) wsum[wid] = x;
        __syncthreads();
        if (wid == 0) {
            int s = wsum[lane];
#pragma unroll
            for (int d = 1; d < 32; d <<= 1) {
                int t = __shfl_up_sync(0xFFFFFFFFu, s, d);
                if (lane >= d) s += t;
            }
            wsum[lane] = s;
        }
        __syncthreads();
        int woff = (wid > 0) ? wsum[wid - 1] : 0;
        int inc = carry_s + woff + x;
        if (i < A) { offs[i + 1] = inc; cursor[i] = inc - v; }
        __syncthreads();
        if (tid == 1023) carry_s = inc;
        __syncthreads();
    }
}

// scatter sorted edge records {rx, ry, rz, dst-as-float-bits}
__global__ void scatter_kernel(const int* __restrict__ src,
                               const int* __restrict__ dst,
                               const float* __restrict__ r_ij,
                               int* __restrict__ cursor,
                               float4* __restrict__ erec, int E) {
    int e = blockIdx.x * blockDim.x + threadIdx.x;
    if (e < E) {
        int p = atomicAdd(&cursor[src[e]], 1);
        float4 rec;
        rec.x = r_ij[3 * e + 0];
        rec.y = r_ij[3 * e + 1];
        rec.z = r_ij[3 * e + 2];
        rec.w = __int_as_float(dst[e]);
        erec[p] = rec;
    }
}

// ---------------------------------------------------------------------------
// fp32 SIMT GEMM for the table build: BM=16, BN=256, BK=32.
template <int K, bool SILU, bool HALF_OUT>
__global__ void __launch_bounds__(256) mlp_small(
    const float* __restrict__ A, const float* __restrict__ W,
    const float* __restrict__ bias, void* __restrict__ Cout, int M)
{
    constexpr int BM = 16, BK = 32;
    __shared__ float As[BM][BK + 1];
    __shared__ float Ws[BK][256];

    const int m0 = blockIdx.x * BM;
    const int tid = threadIdx.x;
    const int tx = tid & 63;
    const int ty = tid >> 6;

    float acc[4][4];
#pragma unroll
    for (int i = 0; i < 4; i++)
#pragma unroll
        for (int j = 0; j < 4; j++) acc[i][j] = 0.0f;

    for (int k0 = 0; k0 < K; k0 += BK) {
        {
            int r = tid >> 4, c2 = (tid & 15) * 2;
            int row = m0 + r;
            float2 v = (row < M) ? *(const float2*)&A[(size_t)row * K + k0 + c2]
                                 : make_float2(0.f, 0.f);
            As[r][c2] = v.x; As[r][c2 + 1] = v.y;
        }
#pragma unroll
        for (int s = 0; s < 8; s++) {
            int f4 = s * 256 + tid;
            int r = f4 >> 6, c4 = f4 & 63;
            float4 w = *(const float4*)&W[(size_t)(k0 + r) * 256 + c4 * 4];
            *(float4*)&Ws[r][c4 * 4] = w;
        }
        __syncthreads();

#pragma unroll
        for (int kk = 0; kk < BK; kk++) {
            float4 w = *(const float4*)&Ws[kk][tx * 4];
            float a0 = As[ty * 4 + 0][kk];
            float a1 = As[ty * 4 + 1][kk];
            float a2 = As[ty * 4 + 2][kk];
            float a3 = As[ty * 4 + 3][kk];
            acc[0][0] += a0 * w.x; acc[0][1] += a0 * w.y;
            acc[0][2] += a0 * w.z; acc[0][3] += a0 * w.w;
            acc[1][0] += a1 * w.x; acc[1][1] += a1 * w.y;
            acc[1][2] += a1 * w.z; acc[1][3] += a1 * w.w;
            acc[2][0] += a2 * w.x; acc[2][1] += a2 * w.y;
            acc[2][2] += a2 * w.z; acc[2][3] += a2 * w.w;
            acc[3][0] += a3 * w.x; acc[3][1] += a3 * w.y;
            acc[3][2] += a3 * w.z; acc[3][3] += a3 * w.w;
        }
        __syncthreads();
    }

    float4 b4 = *(const float4*)&bias[tx * 4];
#pragma unroll
    for (int mi = 0; mi < 4; mi++) {
        int row = m0 + ty * 4 + mi;
        if (row >= M) continue;
        float o[4];
        o[0] = acc[mi][0] + b4.x; o[1] = acc[mi][1] + b4.y;
        o[2] = acc[mi][2] + b4.z; o[3] = acc[mi][3] + b4.w;
        if (SILU) {
#pragma unroll
            for (int j = 0; j < 4; j++) o[j] = o[j] / (1.0f + expf(-o[j]));
        }
        if (HALF_OUT) {
            __half* C = (__half*)Cout;
#pragma unroll
            for (int j = 0; j < 4; j++) {
                int c = tx * 4 + j;
                int i = c & 63, g = c >> 6;
                __half hv = __float2half(o[j]);
                C[((size_t)row * 64 + i) * 8 + g] = hv;
                if (row > 0)
                    C[((size_t)(row - 1) * 64 + i) * 8 + 4 + g] = hv;
            }
        } else {
            float* C = (float*)Cout;
            *(float4*)&C[(size_t)row * 256 + tx * 4] =
                make_float4(o[0], o[1], o[2], o[3]);
        }
    }
}

// ---------------------------------------------------------------------------
// fp16 m16n8k16 fused 3-layer actv MLP, BM=64, 256 threads, 2 CTAs/SM
// (R13 proven config). Weights pre-converted to fp16 -> staging is a pure
// 16B copy loop (half the L2 bytes, no CVT chain).
__device__ __forceinline__ void do_layer_h(
    const __half* __restrict__ WH, int K,
    __half* sA, __half* sW,
    int tid, int wm, int wn, int gid, int tig,
    float acc[2][8][4])
{
#pragma unroll
    for (int mi = 0; mi < 2; mi++)
#pragma unroll
        for (int ni = 0; ni < 8; ni++)
#pragma unroll
            for (int c = 0; c < 4; c++) acc[mi][ni][c] = 0.0f;

    const unsigned short* sWu = (const unsigned short*)sW;
    const int nch = K >> 5;
    for (int ch = 0; ch < nch; ch++) {
        // stage W chunk [32 x 256] fp16: 1024 x 16B copies, 4 per thread
        const uint4* Wsrc = (const uint4*)(WH + (size_t)ch * 32 * 256);
#pragma unroll
        for (int t = tid; t < 1024; t += 256) {
            int r = t >> 5, g = t & 31;      // row, 8-half group
            uint4 v = Wsrc[r * 32 + g];
            *(uint4*)&sW[r * HAST + g * 8] = v;
        }
        __syncthreads();

#pragma unroll
        for (int ks = 0; ks < 2; ks++) {
            const int k0 = ch * 32 + ks * 16;  // sA col base
            const int kw = ks * 16;            // sW row base
            uint32_t a[2][4], b[8][2];
#pragma unroll
            for (int mi = 0; mi < 2; mi++) {
                int row = wm + mi * 16 + gid;
                a[mi][0] = *(const uint32_t*)&sA[row * HAST + k0 + 2 * tig];
                a[mi][1] = *(const uint32_t*)&sA[(row + 8) * HAST + k0 + 2 * tig];
                a[mi][2] = *(const uint32_t*)&sA[row * HAST + k0 + 2 * tig + 8];
                a[mi][3] = *(const uint32_t*)&sA[(row + 8) * HAST + k0 + 2 * tig + 8];
            }
#pragma unroll
            for (int ni = 0; ni < 8; ni++) {
                int n = wn + ni * 8 + gid;
                uint32_t lo0 = sWu[(kw + 2 * tig) * HAST + n];
                uint32_t hi0 = sWu[(kw + 2 * tig + 1) * HAST + n];
                uint32_t lo1 = sWu[(kw + 2 * tig + 8) * HAST + n];
                uint32_t hi1 = sWu[(kw + 2 * tig + 9) * HAST + n];
                b[ni][0] = lo0 | (hi0 << 16);
                b[ni][1] = lo1 | (hi1 << 16);
            }
#pragma unroll
            for (int mi = 0; mi < 2; mi++)
#pragma unroll
                for (int ni = 0; ni < 8; ni++)
                    asm volatile(
                        "mma.sync.aligned.m16n8k16.row.col.f32.f16.f16.f32 "
                        "{%0,%1,%2,%3}, {%4,%5,%6,%7}, {%8,%9}, {%0,%1,%2,%3};"
                        : "+f"(acc[mi][ni][0]), "+f"(acc[mi][ni][1]),
                          "+f"(acc[mi][ni][2]), "+f"(acc[mi][ni][3])
                        : "r"(a[mi][0]), "r"(a[mi][1]), "r"(a[mi][2]), "r"(a[mi][3]),
                          "r"(b[ni][0]), "r"(b[ni][1]));
        }
        __syncthreads();
    }
}

__global__ void __launch_bounds__(256, 2) fused_mlp_actv(
    const float* __restrict__ in,
    const __half* __restrict__ W1, const float* __restrict__ b1,
    const __half* __restrict__ W2, const float* __restrict__ b2,
    const __half* __restrict__ W3, const float* __restrict__ b3,
    __half* __restrict__ axH, int M)
{
    extern __shared__ char smraw[];
    __half* sA  = (__half*)smraw;                       // 64*HAST halfs
    __half* sW  = sA + 64 * HAST;                       // 32*HAST halfs
    float*  sb1 = (float*)(sW + 32 * HAST);
    float*  sb2 = sb1 + 256;
    float*  sb3 = sb2 + 256;

    const int tid = threadIdx.x;
    const int lane = tid & 31;
    const int w = tid >> 5;
    const int gid = lane >> 2, tig = lane & 3;
    const int wm = (w >> 2) * 32, wn = (w & 3) * 64;
    const int m0 = blockIdx.x * 64;

    sb1[tid] = b1[tid]; sb2[tid] = b2[tid]; sb3[tid] = b3[tid];

    // stage input rows (64 x 64 fp32 -> half): 4 threads/row, 16 halfs each
    {
        int r = tid >> 2;
        int cb = (tid & 3) * 16;
        int row = m0 + r;
        __half* ar = &sA[r * HAST + cb];
#pragma unroll
        for (int q = 0; q < 4; q++) {
            float4 v = (row < M)
                ? *(const float4*)&in[(size_t)row * 64 + cb + q * 4]
                : make_float4(0.f, 0.f, 0.f, 0.f);
            *(uint2*)&ar[q * 4] = make_uint2(pack_half2(v.x, v.y),
                                             pack_half2(v.z, v.w));
        }
    }
    __syncthreads();

    float acc[2][8][4];

    do_layer_h(W1, 64, sA, sW, tid, wm, wn, gid, tig, acc);
#pragma unroll
    for (int mi = 0; mi < 2; mi++) {
        int r0 = wm + mi * 16 + gid;
#pragma unroll
        for (int ni = 0; ni < 8; ni++) {
            int c0 = wn + ni * 8 + 2 * tig;
            float bb0 = sb1[c0], bb1 = sb1[c0 + 1];
            *(uint32_t*)&sA[r0 * HAST + c0] =
                pack_half2(silu_fast(acc[mi][ni][0] + bb0),
                           silu_fast(acc[mi][ni][1] + bb1));
            *(uint32_t*)&sA[(r0 + 8) * HAST + c0] =
                pack_half2(silu_fast(acc[mi][ni][2] + bb0),
                           silu_fast(acc[mi][ni][3] + bb1));
        }
    }
    __syncthreads();

    do_layer_h(W2, 256, sA, sW, tid, wm, wn, gid, tig, acc);
#pragma unroll
    for (int mi = 0; mi < 2; mi++) {
        int r0 = wm + mi * 16 + gid;
#pragma unroll
        for (int ni = 0; ni < 8; ni++) {
            int c0 = wn + ni * 8 + 2 * tig;
            float bb0 = sb2[c0], bb1 = sb2[c0 + 1];
            *(uint32_t*)&sA[r0 * HAST + c0] =
                pack_half2(silu_fast(acc[mi][ni][0] + bb0),
                           silu_fast(acc[mi][ni][1] + bb1));
            *(uint32_t*)&sA[(r0 + 8) * HAST + c0] =
                pack_half2(silu_fast(acc[mi][ni][2] + bb0),
                           silu_fast(acc[mi][ni][3] + bb1));
        }
    }
    __syncthreads();

    do_layer_h(W3, 256, sA, sW, tid, wm, wn, gid, tig, acc);
#pragma unroll
    for (int mi = 0; mi < 2; mi++) {
        int r0 = wm + mi * 16 + gid;
#pragma unroll
        for (int ni = 0; ni < 8; ni++) {
            int c0 = wn + ni * 8 + 2 * tig;
            float bb0 = sb3[c0], bb1 = sb3[c0 + 1];
#pragma unroll
            for (int half = 0; half < 2; half++) {
                int row = m0 + r0 + half * 8;
                if (row >= M) continue;
                float v0 = acc[mi][ni][half * 2 + 0] + bb0;
                float v1 = acc[mi][ni][half * 2 + 1] + bb1;
                axH[((size_t)row * 64 + (c0 & 63)) * 8 + (c0 >> 6)] = __float2half(v0);
                axH[((size_t)row * 64 + ((c0 + 1) & 63)) * 8 + ((c0 + 1) >> 6)] = __float2half(v1);
            }
        }
    }
}

// ---------------------------------------------------------------------------
// atomic-free epilogue: 256 threads per src atom (4 quarters x 64 channels).
__global__ void __launch_bounds__(256) epilogue_quad(
    const __half* __restrict__ tblP,   // [TBL][64][8]
    const __half* __restrict__ axH,    // [B*A][64][8]
    const float4* __restrict__ erec,   // [E] sorted {rx,ry,rz,dst}
    const int* __restrict__ offs,      // [A+1]
    float* __restrict__ out_a, float* __restrict__ out_v,
    int A)
{
    __shared__ float red[4][64][17];

    const int a = blockIdx.x;
    const int q = threadIdx.x >> 6;
    const int i = threadIdx.x & 63;

    const int p0 = offs[a], p1 = offs[a + 1];

    float accx[B_DIM], accy[B_DIM], accz[B_DIM], acca[B_DIM];
#pragma unroll
    for (int b = 0; b < B_DIM; b++) {
        accx[b] = 0.f; accy[b] = 0.f; accz[b] = 0.f; acca[b] = 0.f;
    }

    int p = p0 + q;
    float4 rec = make_float4(0.f, 0.f, 0.f, 0.f);
    if (p < p1) rec = __ldg(&erec[p]);

    for (; p < p1; p += 4) {
        float4 rec_n = make_float4(0.f, 0.f, 0.f, 0.f);
        if (p + 4 < p1) rec_n = __ldg(&erec[p + 4]);

        float rx = rec.x, ry = rec.y, rz = rec.z;
        int ad = __float_as_int(rec.w);

        float r2 = rx * rx + ry * ry + rz * rz;
        float d  = sqrtf(r2);
        float inv = rsqrtf(0.1f + r2);
        float dx = rx * inv, dy = ry * inv, dz = rz * inv;

        float u = fminf(d * INV_STEP, (float)(TBL - 1) - 0.001f);
        int   i0 = (int)u;
        float fr = u - (float)i0;

        uint4 tp = *(const uint4*)(tblP + ((size_t)i0 * 64 + i) * 8);
        float2 c01 = __half22float2(*(__half2*)&tp.x);
        float2 c23 = __half22float2(*(__half2*)&tp.y);
        float2 n01 = __half22float2(*(__half2*)&tp.z);
        float2 n23 = __half22float2(*(__half2*)&tp.w);
        float d0 = c01.x + fr * (n01.x - c01.x);
        float d1 = c01.y + fr * (n01.y - c01.y);
        float d2 = c23.x + fr * (n23.x - c23.x);
        float d3 = c23.y + fr * (n23.y - c23.y);

#pragma unroll
        for (int b = 0; b < B_DIM; b++) {
            uint4 pk = *(const uint4*)(axH + (((size_t)b * A + ad) * 64 + i) * 8);
            float2 a01 = __half22float2(*(__half2*)&pk.x);
            float2 a23 = __half22float2(*(__half2*)&pk.y);
            float2 vxy = __half22float2(*(__half2*)&pk.z);
            float2 vzp = __half22float2(*(__half2*)&pk.w);
            float q0 = d0 * a01.x;
            float q1 = d1 * a01.y;
            float q2 = d2 * a23.x;
            float q3 = d3 * a23.y;
            float vx = vxy.x, vy = vxy.y, vz = vzp.x;

            float cx = vy * dz - vz * dy;
            float cy = vz * dx - vx * dz;
            float cz = vx * dy - vy * dx;

            accx[b] += vx * q0 + cx * q1 + dx * q2;
            accy[b] += vy * q0 + cy * q1 + dy * q2;
            accz[b] += vz * q0 + cz * q1 + dz * q2;
            acca[b] += q3;
        }

        rec = rec_n;
    }

#pragma unroll
    for (int b = 0; b < B_DIM; b++) {
        red[q][i][b * 4 + 0] = accx[b];
        red[q][i][b * 4 + 1] = accy[b];
        red[q][i][b * 4 + 2] = accz[b];
        red[q][i][b * 4 + 3] = acca[b];
    }
    __syncthreads();

    {
        int b = q;
        float sx = red[0][i][b * 4 + 0] + red[1][i][b * 4 + 0]
                 + red[2][i][b * 4 + 0] + red[3][i][b * 4 + 0];
        float sy = red[0][i][b * 4 + 1] + red[1][i][b * 4 + 1]
                 + red[2][i][b * 4 + 1] + red[3][i][b * 4 + 1];
        float sz = red[0][i][b * 4 + 2] + red[1][i][b * 4 + 2]
                 + red[2][i][b * 4 + 2] + red[3][i][b * 4 + 2];
        float sa = red[0][i][b * 4 + 3] + red[1][i][b * 4 + 3]
                 + red[2][i][b * 4 + 3] + red[3][i][b * 4 + 3];
        size_t ob = (((size_t)b * A + a) * 64 + i) * 3;
        out_v[ob + 0] = sx;
        out_v[ob + 1] = sy;
        out_v[ob + 2] = sz;
        out_a[((size_t)b * A + a) * 64 + i] = sa;
    }
}

// ---------------------------------------------------------------------------
#define SMEM_MLP ((64 * HAST + 32 * HAST) * 2 + 3 * 256 * 4)

extern "C" void kernel_launch(void* const* d_in, const int* in_sizes, int n_in,
                              void* d_out, int out_size) {
    const float* x_a  = (const float*)d_in[0];
    const float* x_v  = (const float*)d_in[1];
    const float* r_ij = (const float*)d_in[2];
    const int*   src  = (const int*)d_in[3];
    const int*   dst  = (const int*)d_in[4];
    const float* dW1 = (const float*)d_in[5];
    const float* db1 = (const float*)d_in[6];
    const float* dW2 = (const float*)d_in[7];
    const float* db2 = (const float*)d_in[8];
    const float* dW3 = (const float*)d_in[9];
    const float* db3 = (const float*)d_in[10];
    const float* aW1 = (const float*)d_in[11];
    const float* ab1 = (const float*)d_in[12];
    const float* aW2 = (const float*)d_in[13];
    const float* ab2 = (const float*)d_in[14];
    const float* aW3 = (const float*)d_in[15];
    const float* ab3 = (const float*)d_in[16];

    const int E  = in_sizes[3];
    const int BA = in_sizes[0] / NCH;
    const int A  = BA / B_DIM;

    float *enc, *tmpA, *tmpB;
    float4* erec;
    __half *axH, *tblP, *w1H, *w2H, *w3H;
    int *hist, *offs, *cursor;
    cudaGetSymbolAddress((void**)&axH,    g_axH);
    cudaGetSymbolAddress((void**)&tblP,   g_tblP);
    cudaGetSymbolAddress((void**)&enc,    g_enc);
    cudaGetSymbolAddress((void**)&tmpA,   g_tmpA);
    cudaGetSymbolAddress((void**)&tmpB,   g_tmpB);
    cudaGetSymbolAddress((void**)&erec,   g_erec);
    cudaGetSymbolAddress((void**)&w1H,    g_w1H);
    cudaGetSymbolAddress((void**)&w2H,    g_w2H);
    cudaGetSymbolAddress((void**)&w3H,    g_w3H);
    cudaGetSymbolAddress((void**)&hist,   g_hist);
    cudaGetSymbolAddress((void**)&offs,   g_offs);
    cudaGetSymbolAddress((void**)&cursor, g_cursor);

    // One-time resource setup (first call happens before the harness's
    // pre-capture memory baseline; capture call creates nothing).
    static cudaStream_t s1 = nullptr, s2 = nullptr;
    static cudaEvent_t evRoot = nullptr, ev1 = nullptr, ev2 = nullptr;
    if (s1 == nullptr) {
        cudaStreamCreateWithFlags(&s1, cudaStreamNonBlocking);
        cudaStreamCreateWithFlags(&s2, cudaStreamNonBlocking);
        cudaEventCreateWithFlags(&evRoot, cudaEventDisableTiming);
        cudaEventCreateWithFlags(&ev1, cudaEventDisableTiming);
        cudaEventCreateWithFlags(&ev2, cudaEventDisableTiming);
        cudaFuncSetAttribute(fused_mlp_actv,
            cudaFuncAttributeMaxDynamicSharedMemorySize, SMEM_MLP);
    }

    float* out_a = (float*)d_out;
    float* out_v = out_a + (size_t)BA * NCH;

    // Fork side streams off the origin stream (capture-legal: events only).
    cudaEventRecord(evRoot, 0);
    cudaStreamWaitEvent(s1, evRoot, 0);
    cudaStreamWaitEvent(s2, evRoot, 0);

    // ---- stream 0 (origin): counting sort chain + xv convert ----
    convert_xv<<<(BA * NCH + 255) / 256, 256>>>(x_v, axH, BA * NCH);
    zero_hist<<<(A + 255) / 256, 256>>>(hist, A);
    hist_kernel<<<(E + 255) / 256, 256>>>(src, hist, E);
    scan_kernel<<<1, 1024>>>(hist, offs, cursor, A);
    scatter_kernel<<<(E + 255) / 256, 256>>>(src, dst, r_ij, cursor, erec, E);

    // ---- stream 1: weight fp16 pre-convert + actv MLP (fp16 tensor cores) ----
    convert_w<<<(NCH * HID / 2 + 255) / 256, 256, 0, s1>>>(aW1, w1H, NCH * HID / 2);
    convert_w<<<(HID * HID / 2 + 255) / 256, 256, 0, s1>>>(aW2, w2H, HID * HID / 2);
    convert_w<<<(HID * HID / 2 + 255) / 256, 256, 0, s1>>>(aW3, w3H, HID * HID / 2);
    fused_mlp_actv<<<(BA + 63) / 64, 256, SMEM_MLP, s1>>>(
        x_a, w1H, ab1, w2H, ab2, w3H, ab3, axH, BA);

    // ---- stream 2: dist-table build (FFMA pipe) ----
    encode_table<<<(TBL * 64 + 255) / 256, 256, 0, s2>>>(enc);
    mlp_small<64,  true,  false><<<TBL / 16, 256, 0, s2>>>(enc,  dW1, db1, tmpA, TBL);
    mlp_small<256, true,  false><<<TBL / 16, 256, 0, s2>>>(tmpA, dW2, db2, tmpB, TBL);
    mlp_small<256, false, true ><<<TBL / 16, 256, 0, s2>>>(tmpB, dW3, db3, tblP, TBL);

    // ---- join ----
    cudaEventRecord(ev1, s1);
    cudaEventRecord(ev2, s2);
    cudaStreamWaitEvent(0, ev1, 0);
    cudaStreamWaitEvent(0, ev2, 0);

    // ---- epilogue on origin stream ----
    epilogue_quad<<<A, 256>>>(tblP, axH, erec, offs, out_a, out_v, A);
}

// round 17
// speedup vs baseline: 1.1379x; 1.0291x over previous
#include <cuda_runtime.h>
#include <cuda_fp16.h>
#include <math.h>
#include <stdint.h>

// Problem constants
#define E_MAX   320000
#define A_MAX   10000
#define B_DIM   4
#define NCH     64
#define HID     256
#define HAST    264   // half-element smem row stride (even, 8-half aligned)

// dist-MLP lookup table
#define TBL     1024
#define D_MAX   8.0f
#define DSTEP   (D_MAX / (float)TBL)
#define INV_STEP ((float)TBL / D_MAX)

// Scratch (static __device__; allocation APIs forbidden)
__device__ __align__(16) __half g_axH [B_DIM * A_MAX * NCH * 8];
__device__ __align__(16) __half g_tblP[TBL * NCH * 8];
__device__ __align__(16) float  g_enc [TBL * NCH];
__device__ __align__(16) float  g_tmpA[TBL * HID];
__device__ __align__(16) float  g_tmpB[TBL * HID];
__device__ __align__(16) float4 g_erec[E_MAX];   // sorted edge records {rx,ry,rz,dst}
__device__ __align__(16) __half g_w1H[NCH * HID];   // actv weights, fp16
__device__ __align__(16) __half g_w2H[HID * HID];
__device__ __align__(16) __half g_w3H[HID * HID];
__device__ int g_hist  [A_MAX];
__device__ int g_offs  [A_MAX + 1];
__device__ int g_cursor[A_MAX];

// ---------------------------------------------------------------------------
__device__ __forceinline__ float silu_fast(float v) {
    return v / (1.0f + __expf(-v));
}
__device__ __forceinline__ uint32_t pack_half2(float lo, float hi) {
    __half2 h = __floats2half2_rn(lo, hi);
    return *(uint32_t*)&h;
}
__device__ __forceinline__ uint32_t smem_u32(const void* p) {
    uint32_t a;
    asm("{ .reg .u64 t; cvta.to.shared.u64 t, %1; cvt.u32.u64 %0, t; }"
        : "=r"(a) : "l"(p));
    return a;
}
__device__ __forceinline__ void cp_async16(uint32_t saddr, const void* gaddr) {
    asm volatile("cp.async.ca.shared.global [%0], [%1], 16;"
                 :: "r"(saddr), "l"(gaddr) : "memory");
}
#define CP_COMMIT() asm volatile("cp.async.commit_group;" ::: "memory")
#define CP_WAIT0()  asm volatile("cp.async.wait_group 0;" ::: "memory")

// ---------------------------------------------------------------------------
__global__ void zero_hist(int* __restrict__ hist, int A) {
    int t = blockIdx.x * blockDim.x + threadIdx.x;
    if (t < A) hist[t] = 0;
}

__global__ void convert_xv(const float* __restrict__ x_v, __half* __restrict__ axH,
                           int n) {
    int t = blockIdx.x * blockDim.x + threadIdx.x;
    if (t >= n) return;
    float vx = x_v[3 * t + 0];
    float vy = x_v[3 * t + 1];
    float vz = x_v[3 * t + 2];
    __half2* dp = (__half2*)(axH + (size_t)t * 8 + 4);
    dp[0] = __floats2half2_rn(vx, vy);
    dp[1] = __floats2half2_rn(vz, 0.0f);
}

// fp32 -> fp16 weight conversion, all three actv layers in one launch
__global__ void convert_w3(const float* __restrict__ W1,
                           const float* __restrict__ W2,
                           const float* __restrict__ W3,
                           __half* __restrict__ w1H,
                           __half* __restrict__ w2H,
                           __half* __restrict__ w3H) {
    const int n1 = NCH * HID / 2, n2 = HID * HID / 2;
    int t = blockIdx.x * blockDim.x + threadIdx.x;
    if (t < n1) {
        float2 v = *(const float2*)&W1[2 * t];
        ((__half2*)w1H)[t] = __floats2half2_rn(v.x, v.y);
    } else if (t < n1 + n2) {
        int u = t - n1;
        float2 v = *(const float2*)&W2[2 * u];
        ((__half2*)w2H)[u] = __floats2half2_rn(v.x, v.y);
    } else if (t < n1 + 2 * n2) {
        int u = t - n1 - n2;
        float2 v = *(const float2*)&W3[2 * u];
        ((__half2*)w3H)[u] = __floats2half2_rn(v.x, v.y);
    }
}

__global__ void encode_table(float* __restrict__ enc) {
    int t = blockIdx.x * blockDim.x + threadIdx.x;
    if (t >= TBL * 64) return;
    int idx = t >> 6, j = t & 63;
    float d = (float)idx * DSTEP;
    int jj = (j < 32) ? j : (j - 32);
    float c = 0.31415926535897932f * (float)(1 + (jj >> 1));
    float ph = c * d;
    enc[t] = (j < 32) ? cosf(ph) : sinf(ph);
}

// ---------------------------------------------------------------------------
__global__ void hist_kernel(const int* __restrict__ src, int* __restrict__ hist, int E) {
    int e = blockIdx.x * blockDim.x + threadIdx.x;
    if (e < E) atomicAdd(&hist[src[e]], 1);
}

// shfl-based block scan, 1024 threads, chunked over A
__global__ void scan_kernel(const int* __restrict__ hist, int* __restrict__ offs,
                            int* __restrict__ cursor, int A) {
    __shared__ int wsum[32];
    __shared__ int carry_s;
    int tid = threadIdx.x, lane = tid & 31, wid = tid >> 5;
    if (tid == 0) { carry_s = 0; offs[0] = 0; }
    __syncthreads();
    for (int base = 0; base < A; base += 1024) {
        int i = base + tid;
        int v = (i < A) ? hist[i] : 0;
        int x = v;
#pragma unroll
        for (int d = 1; d < 32; d <<= 1) {
            int t = __shfl_up_sync(0xFFFFFFFFu, x, d);
            if (lane >= d) x += t;
        }
        if (lane == 31) wsum[wid] = x;
        __syncthreads();
        if (wid == 0) {
            int s = wsum[lane];
#pragma unroll
            for (int d = 1; d < 32; d <<= 1) {
                int t = __shfl_up_sync(0xFFFFFFFFu, s, d);
                if (lane >= d) s += t;
            }
            wsum[lane] = s;
        }
        __syncthreads();
        int woff = (wid > 0) ? wsum[wid - 1] : 0;
        int inc = carry_s + woff + x;
        if (i < A) { offs[i + 1] = inc; cursor[i] = inc - v; }
        __syncthreads();
        if (tid == 1023) carry_s = inc;
        __syncthreads();
    }
}

// scatter sorted edge records {rx, ry, rz, dst-as-float-bits}
__global__ void scatter_kernel(const int* __restrict__ src,
                               const int* __restrict__ dst,
                               const float* __restrict__ r_ij,
                               int* __restrict__ cursor,
                               float4* __restrict__ erec, int E) {
    int e = blockIdx.x * blockDim.x + threadIdx.x;
    if (e < E) {
        int p = atomicAdd(&cursor[src[e]], 1);
        float4 rec;
        rec.x = r_ij[3 * e + 0];
        rec.y = r_ij[3 * e + 1];
        rec.z = r_ij[3 * e + 2];
        rec.w = __int_as_float(dst[e]);
        erec[p] = rec;
    }
}

// ---------------------------------------------------------------------------
// fp32 SIMT GEMM for the table build: BM=16, BN=256, BK=32.
template <int K, bool SILU, bool HALF_OUT>
__global__ void __launch_bounds__(256) mlp_small(
    const float* __restrict__ A, const float* __restrict__ W,
    const float* __restrict__ bias, void* __restrict__ Cout, int M)
{
    constexpr int BM = 16, BK = 32;
    __shared__ float As[BM][BK + 1];
    __shared__ float Ws[BK][256];

    const int m0 = blockIdx.x * BM;
    const int tid = threadIdx.x;
    const int tx = tid & 63;
    const int ty = tid >> 6;

    float acc[4][4];
#pragma unroll
    for (int i = 0; i < 4; i++)
#pragma unroll
        for (int j = 0; j < 4; j++) acc[i][j] = 0.0f;

    for (int k0 = 0; k0 < K; k0 += BK) {
        {
            int r = tid >> 4, c2 = (tid & 15) * 2;
            int row = m0 + r;
            float2 v = (row < M) ? *(const float2*)&A[(size_t)row * K + k0 + c2]
                                 : make_float2(0.f, 0.f);
            As[r][c2] = v.x; As[r][c2 + 1] = v.y;
        }
#pragma unroll
        for (int s = 0; s < 8; s++) {
            int f4 = s * 256 + tid;
            int r = f4 >> 6, c4 = f4 & 63;
            float4 w = *(const float4*)&W[(size_t)(k0 + r) * 256 + c4 * 4];
            *(float4*)&Ws[r][c4 * 4] = w;
        }
        __syncthreads();

#pragma unroll
        for (int kk = 0; kk < BK; kk++) {
            float4 w = *(const float4*)&Ws[kk][tx * 4];
            float a0 = As[ty * 4 + 0][kk];
            float a1 = As[ty * 4 + 1][kk];
            float a2 = As[ty * 4 + 2][kk];
            float a3 = As[ty * 4 + 3][kk];
            acc[0][0] += a0 * w.x; acc[0][1] += a0 * w.y;
            acc[0][2] += a0 * w.z; acc[0][3] += a0 * w.w;
            acc[1][0] += a1 * w.x; acc[1][1] += a1 * w.y;
            acc[1][2] += a1 * w.z; acc[1][3] += a1 * w.w;
            acc[2][0] += a2 * w.x; acc[2][1] += a2 * w.y;
            acc[2][2] += a2 * w.z; acc[2][3] += a2 * w.w;
            acc[3][0] += a3 * w.x; acc[3][1] += a3 * w.y;
            acc[3][2] += a3 * w.z; acc[3][3] += a3 * w.w;
        }
        __syncthreads();
    }

    float4 b4 = *(const float4*)&bias[tx * 4];
#pragma unroll
    for (int mi = 0; mi < 4; mi++) {
        int row = m0 + ty * 4 + mi;
        if (row >= M) continue;
        float o[4];
        o[0] = acc[mi][0] + b4.x; o[1] = acc[mi][1] + b4.y;
        o[2] = acc[mi][2] + b4.z; o[3] = acc[mi][3] + b4.w;
        if (SILU) {
#pragma unroll
            for (int j = 0; j < 4; j++) o[j] = o[j] / (1.0f + expf(-o[j]));
        }
        if (HALF_OUT) {
            __half* C = (__half*)Cout;
#pragma unroll
            for (int j = 0; j < 4; j++) {
                int c = tx * 4 + j;
                int i = c & 63, g = c >> 6;
                __half hv = __float2half(o[j]);
                C[((size_t)row * 64 + i) * 8 + g] = hv;
                if (row > 0)
                    C[((size_t)(row - 1) * 64 + i) * 8 + 4 + g] = hv;
            }
        } else {
            float* C = (float*)Cout;
            *(float4*)&C[(size_t)row * 256 + tx * 4] =
                make_float4(o[0], o[1], o[2], o[3]);
        }
    }
}

// ---------------------------------------------------------------------------
// fp16 m16n8k16 fused 3-layer actv MLP, BM=64, 256 threads, 2 CTAs/SM.
// Weight staging via cp.async DOUBLE BUFFER: issue async copies for chunk
// c+1 (no register round-trip, no scoreboard stall), run MMAs of chunk c,
// then wait_group + barrier. Staging latency overlaps the math.
__device__ __forceinline__ void stage_async(
    const __half* __restrict__ WH, int ch, uint32_t buf_u32, int tid)
{
    const uint4* Wsrc = (const uint4*)(WH + (size_t)ch * 32 * 256);
#pragma unroll
    for (int t = tid; t < 1024; t += 256) {
        int r = t >> 5, g = t & 31;      // row, 8-half group
        cp_async16(buf_u32 + (uint32_t)(r * HAST + g * 8) * 2, Wsrc + r * 32 + g);
    }
    CP_COMMIT();
}

__device__ __forceinline__ void do_layer_h(
    const __half* __restrict__ WH, int K,
    __half* sA, __half* sW, uint32_t sW_u32,
    int tid, int wm, int wn, int gid, int tig,
    float acc[2][8][4])
{
#pragma unroll
    for (int mi = 0; mi < 2; mi++)
#pragma unroll
        for (int ni = 0; ni < 8; ni++)
#pragma unroll
            for (int c = 0; c < 4; c++) acc[mi][ni][c] = 0.0f;

    const int nch = K >> 5;
    stage_async(WH, 0, sW_u32, tid);
    CP_WAIT0();
    __syncthreads();

    for (int ch = 0; ch < nch; ch++) {
        const unsigned short* sWu =
            (const unsigned short*)(sW + (ch & 1) * 32 * HAST);
        bool more = (ch + 1 < nch);
        if (more)
            stage_async(WH, ch + 1,
                        sW_u32 + (uint32_t)(((ch + 1) & 1) * 32 * HAST) * 2, tid);

#pragma unroll
        for (int ks = 0; ks < 2; ks++) {
            const int k0 = ch * 32 + ks * 16;  // sA col base
            const int kw = ks * 16;            // cur row base
            uint32_t a[2][4], b[8][2];
#pragma unroll
            for (int mi = 0; mi < 2; mi++) {
                int row = wm + mi * 16 + gid;
                a[mi][0] = *(const uint32_t*)&sA[row * HAST + k0 + 2 * tig];
                a[mi][1] = *(const uint32_t*)&sA[(row + 8) * HAST + k0 + 2 * tig];
                a[mi][2] = *(const uint32_t*)&sA[row * HAST + k0 + 2 * tig + 8];
                a[mi][3] = *(const uint32_t*)&sA[(row + 8) * HAST + k0 + 2 * tig + 8];
            }
#pragma unroll
            for (int ni = 0; ni < 8; ni++) {
                int n = wn + ni * 8 + gid;
                uint32_t lo0 = sWu[(kw + 2 * tig) * HAST + n];
                uint32_t hi0 = sWu[(kw + 2 * tig + 1) * HAST + n];
                uint32_t lo1 = sWu[(kw + 2 * tig + 8) * HAST + n];
                uint32_t hi1 = sWu[(kw + 2 * tig + 9) * HAST + n];
                b[ni][0] = lo0 | (hi0 << 16);
                b[ni][1] = lo1 | (hi1 << 16);
            }
#pragma unroll
            for (int mi = 0; mi < 2; mi++)
#pragma unroll
                for (int ni = 0; ni < 8; ni++)
                    asm volatile(
                        "mma.sync.aligned.m16n8k16.row.col.f32.f16.f16.f32 "
                        "{%0,%1,%2,%3}, {%4,%5,%6,%7}, {%8,%9}, {%0,%1,%2,%3};"
                        : "+f"(acc[mi][ni][0]), "+f"(acc[mi][ni][1]),
                          "+f"(acc[mi][ni][2]), "+f"(acc[mi][ni][3])
                        : "r"(a[mi][0]), "r"(a[mi][1]), "r"(a[mi][2]), "r"(a[mi][3]),
                          "r"(b[ni][0]), "r"(b[ni][1]));
        }
        if (more) CP_WAIT0();
        __syncthreads();
    }
}

__global__ void __launch_bounds__(256, 2) fused_mlp_actv(
    const float* __restrict__ in,
    const __half* __restrict__ W1, const float* __restrict__ b1,
    const __half* __restrict__ W2, const float* __restrict__ b2,
    const __half* __restrict__ W3, const float* __restrict__ b3,
    __half* __restrict__ axH, int M)
{
    extern __shared__ char smraw[];
    __half* sA  = (__half*)smraw;                       // 64*HAST halfs
    __half* sW  = sA + 64 * HAST;                       // 2 x 32*HAST halfs
    float*  sb1 = (float*)(sW + 64 * HAST);
    float*  sb2 = sb1 + 256;
    float*  sb3 = sb2 + 256;
    const uint32_t sW_u32 = smem_u32(sW);

    const int tid = threadIdx.x;
    const int lane = tid & 31;
    const int w = tid >> 5;
    const int gid = lane >> 2, tig = lane & 3;
    const int wm = (w >> 2) * 32, wn = (w & 3) * 64;
    const int m0 = blockIdx.x * 64;

    sb1[tid] = b1[tid]; sb2[tid] = b2[tid]; sb3[tid] = b3[tid];

    // stage input rows (64 x 64 fp32 -> half): 4 threads/row, 16 halfs each
    {
        int r = tid >> 2;
        int cb = (tid & 3) * 16;
        int row = m0 + r;
        __half* ar = &sA[r * HAST + cb];
#pragma unroll
        for (int q = 0; q < 4; q++) {
            float4 v = (row < M)
                ? *(const float4*)&in[(size_t)row * 64 + cb + q * 4]
                : make_float4(0.f, 0.f, 0.f, 0.f);
            *(uint2*)&ar[q * 4] = make_uint2(pack_half2(v.x, v.y),
                                             pack_half2(v.z, v.w));
        }
    }
    __syncthreads();

    float acc[2][8][4];

    do_layer_h(W1, 64, sA, sW, sW_u32, tid, wm, wn, gid, tig, acc);
#pragma unroll
    for (int mi = 0; mi < 2; mi++) {
        int r0 = wm + mi * 16 + gid;
#pragma unroll
        for (int ni = 0; ni < 8; ni++) {
            int c0 = wn + ni * 8 + 2 * tig;
            float bb0 = sb1[c0], bb1 = sb1[c0 + 1];
            *(uint32_t*)&sA[r0 * HAST + c0] =
                pack_half2(silu_fast(acc[mi][ni][0] + bb0),
                           silu_fast(acc[mi][ni][1] + bb1));
            *(uint32_t*)&sA[(r0 + 8) * HAST + c0] =
                pack_half2(silu_fast(acc[mi][ni][2] + bb0),
                           silu_fast(acc[mi][ni][3] + bb1));
        }
    }
    __syncthreads();

    do_layer_h(W2, 256, sA, sW, sW_u32, tid, wm, wn, gid, tig, acc);
#pragma unroll
    for (int mi = 0; mi < 2; mi++) {
        int r0 = wm + mi * 16 + gid;
#pragma unroll
        for (int ni = 0; ni < 8; ni++) {
            int c0 = wn + ni * 8 + 2 * tig;
            float bb0 = sb2[c0], bb1 = sb2[c0 + 1];
            *(uint32_t*)&sA[r0 * HAST + c0] =
                pack_half2(silu_fast(acc[mi][ni][0] + bb0),
                           silu_fast(acc[mi][ni][1] + bb1));
            *(uint32_t*)&sA[(r0 + 8) * HAST + c0] =
                pack_half2(silu_fast(acc[mi][ni][2] + bb0),
                           silu_fast(acc[mi][ni][3] + bb1));
        }
    }
    __syncthreads();

    do_layer_h(W3, 256, sA, sW, sW_u32, tid, wm, wn, gid, tig, acc);
#pragma unroll
    for (int mi = 0; mi < 2; mi++) {
        int r0 = wm + mi * 16 + gid;
#pragma unroll
        for (int ni = 0; ni < 8; ni++) {
            int c0 = wn + ni * 8 + 2 * tig;
            float bb0 = sb3[c0], bb1 = sb3[c0 + 1];
#pragma unroll
            for (int half = 0; half < 2; half++) {
                int row = m0 + r0 + half * 8;
                if (row >= M) continue;
                float v0 = acc[mi][ni][half * 2 + 0] + bb0;
                float v1 = acc[mi][ni][half * 2 + 1] + bb1;
                axH[((size_t)row * 64 + (c0 & 63)) * 8 + (c0 >> 6)] = __float2half(v0);
                axH[((size_t)row * 64 + ((c0 + 1) & 63)) * 8 + ((c0 + 1) >> 6)] = __float2half(v1);
            }
        }
    }
}

// ---------------------------------------------------------------------------
// atomic-free epilogue: 256 threads per src atom (4 quarters x 64 channels).
__global__ void __launch_bounds__(256) epilogue_quad(
    const __half* __restrict__ tblP,   // [TBL][64][8]
    const __half* __restrict__ axH,    // [B*A][64][8]
    const float4* __restrict__ erec,   // [E] sorted {rx,ry,rz,dst}
    const int* __restrict__ offs,      // [A+1]
    float* __restrict__ out_a, float* __restrict__ out_v,
    int A)
{
    __shared__ float red[4][64][17];

    const int a = blockIdx.x;
    const int q = threadIdx.x >> 6;
    const int i = threadIdx.x & 63;

    const int p0 = offs[a], p1 = offs[a + 1];

    float accx[B_DIM], accy[B_DIM], accz[B_DIM], acca[B_DIM];
#pragma unroll
    for (int b = 0; b < B_DIM; b++) {
        accx[b] = 0.f; accy[b] = 0.f; accz[b] = 0.f; acca[b] = 0.f;
    }

    int p = p0 + q;
    float4 rec = make_float4(0.f, 0.f, 0.f, 0.f);
    if (p < p1) rec = __ldg(&erec[p]);

    for (; p < p1; p += 4) {
        float4 rec_n = make_float4(0.f, 0.f, 0.f, 0.f);
        if (p + 4 < p1) rec_n = __ldg(&erec[p + 4]);

        float rx = rec.x, ry = rec.y, rz = rec.z;
        int ad = __float_as_int(rec.w);

        float r2 = rx * rx + ry * ry + rz * rz;
        float d  = sqrtf(r2);
        float inv = rsqrtf(0.1f + r2);
        float dx = rx * inv, dy = ry * inv, dz = rz * inv;

        float u = fminf(d * INV_STEP, (float)(TBL - 1) - 0.001f);
        int   i0 = (int)u;
        float fr = u - (float)i0;

        uint4 tp = *(const uint4*)(tblP + ((size_t)i0 * 64 + i) * 8);
        float2 c01 = __half22float2(*(__half2*)&tp.x);
        float2 c23 = __half22float2(*(__half2*)&tp.y);
        float2 n01 = __half22float2(*(__half2*)&tp.z);
        float2 n23 = __half22float2(*(__half2*)&tp.w);
        float d0 = c01.x + fr * (n01.x - c01.x);
        float d1 = c01.y + fr * (n01.y - c01.y);
        float d2 = c23.x + fr * (n23.x - c23.x);
        float d3 = c23.y + fr * (n23.y - c23.y);

#pragma unroll
        for (int b = 0; b < B_DIM; b++) {
            uint4 pk = *(const uint4*)(axH + (((size_t)b * A + ad) * 64 + i) * 8);
            float2 a01 = __half22float2(*(__half2*)&pk.x);
            float2 a23 = __half22float2(*(__half2*)&pk.y);
            float2 vxy = __half22float2(*(__half2*)&pk.z);
            float2 vzp = __half22float2(*(__half2*)&pk.w);
            float q0 = d0 * a01.x;
            float q1 = d1 * a01.y;
            float q2 = d2 * a23.x;
            float q3 = d3 * a23.y;
            float vx = vxy.x, vy = vxy.y, vz = vzp.x;

            float cx = vy * dz - vz * dy;
            float cy = vz * dx - vx * dz;
            float cz = vx * dy - vy * dx;

            accx[b] += vx * q0 + cx * q1 + dx * q2;
            accy[b] += vy * q0 + cy * q1 + dy * q2;
            accz[b] += vz * q0 + cz * q1 + dz * q2;
            acca[b] += q3;
        }

        rec = rec_n;
    }

#pragma unroll
    for (int b = 0; b < B_DIM; b++) {
        red[q][i][b * 4 + 0] = accx[b];
        red[q][i][b * 4 + 1] = accy[b];
        red[q][i][b * 4 + 2] = accz[b];
        red[q][i][b * 4 + 3] = acca[b];
    }
    __syncthreads();

    {
        int b = q;
        float sx = red[0][i][b * 4 + 0] + red[1][i][b * 4 + 0]
                 + red[2][i][b * 4 + 0] + red[3][i][b * 4 + 0];
        float sy = red[0][i][b * 4 + 1] + red[1][i][b * 4 + 1]
                 + red[2][i][b * 4 + 1] + red[3][i][b * 4 + 1];
        float sz = red[0][i][b * 4 + 2] + red[1][i][b * 4 + 2]
                 + red[2][i][b * 4 + 2] + red[3][i][b * 4 + 2];
        float sa = red[0][i][b * 4 + 3] + red[1][i][b * 4 + 3]
                 + red[2][i][b * 4 + 3] + red[3][i][b * 4 + 3];
        size_t ob = (((size_t)b * A + a) * 64 + i) * 3;
        out_v[ob + 0] = sx;
        out_v[ob + 1] = sy;
        out_v[ob + 2] = sz;
        out_a[((size_t)b * A + a) * 64 + i] = sa;
    }
}

// ---------------------------------------------------------------------------
#define SMEM_MLP ((64 * HAST + 64 * HAST) * 2 + 3 * 256 * 4)

extern "C" void kernel_launch(void* const* d_in, const int* in_sizes, int n_in,
                              void* d_out, int out_size) {
    const float* x_a  = (const float*)d_in[0];
    const float* x_v  = (const float*)d_in[1];
    const float* r_ij = (const float*)d_in[2];
    const int*   src  = (const int*)d_in[3];
    const int*   dst  = (const int*)d_in[4];
    const float* dW1 = (const float*)d_in[5];
    const float* db1 = (const float*)d_in[6];
    const float* dW2 = (const float*)d_in[7];
    const float* db2 = (const float*)d_in[8];
    const float* dW3 = (const float*)d_in[9];
    const float* db3 = (const float*)d_in[10];
    const float* aW1 = (const float*)d_in[11];
    const float* ab1 = (const float*)d_in[12];
    const float* aW2 = (const float*)d_in[13];
    const float* ab2 = (const float*)d_in[14];
    const float* aW3 = (const float*)d_in[15];
    const float* ab3 = (const float*)d_in[16];

    const int E  = in_sizes[3];
    const int BA = in_sizes[0] / NCH;
    const int A  = BA / B_DIM;

    float *enc, *tmpA, *tmpB;
    float4* erec;
    __half *axH, *tblP, *w1H, *w2H, *w3H;
    int *hist, *offs, *cursor;
    cudaGetSymbolAddress((void**)&axH,    g_axH);
    cudaGetSymbolAddress((void**)&tblP,   g_tblP);
    cudaGetSymbolAddress((void**)&enc,    g_enc);
    cudaGetSymbolAddress((void**)&tmpA,   g_tmpA);
    cudaGetSymbolAddress((void**)&tmpB,   g_tmpB);
    cudaGetSymbolAddress((void**)&erec,   g_erec);
    cudaGetSymbolAddress((void**)&w1H,    g_w1H);
    cudaGetSymbolAddress((void**)&w2H,    g_w2H);
    cudaGetSymbolAddress((void**)&w3H,    g_w3H);
    cudaGetSymbolAddress((void**)&hist,   g_hist);
    cudaGetSymbolAddress((void**)&offs,   g_offs);
    cudaGetSymbolAddress((void**)&cursor, g_cursor);

    // One-time resource setup (first call happens before the harness's
    // pre-capture memory baseline; capture call creates nothing).
    static cudaStream_t s1 = nullptr, s2 = nullptr;
    static cudaEvent_t evRoot = nullptr, ev1 = nullptr, ev2 = nullptr;
    if (s1 == nullptr) {
        cudaStreamCreateWithFlags(&s1, cudaStreamNonBlocking);
        cudaStreamCreateWithFlags(&s2, cudaStreamNonBlocking);
        cudaEventCreateWithFlags(&evRoot, cudaEventDisableTiming);
        cudaEventCreateWithFlags(&ev1, cudaEventDisableTiming);
        cudaEventCreateWithFlags(&ev2, cudaEventDisableTiming);
        cudaFuncSetAttribute(fused_mlp_actv,
            cudaFuncAttributeMaxDynamicSharedMemorySize, SMEM_MLP);
    }

    float* out_a = (float*)d_out;
    float* out_v = out_a + (size_t)BA * NCH;

    // Fork side streams off the origin stream (capture-legal: events only).
    cudaEventRecord(evRoot, 0);
    cudaStreamWaitEvent(s1, evRoot, 0);
    cudaStreamWaitEvent(s2, evRoot, 0);

    // ---- stream 0 (origin): counting sort chain + xv convert ----
    convert_xv<<<(BA * NCH + 255) / 256, 256>>>(x_v, axH, BA * NCH);
    zero_hist<<<(A + 255) / 256, 256>>>(hist, A);
    hist_kernel<<<(E + 255) / 256, 256>>>(src, hist, E);
    scan_kernel<<<1, 1024>>>(hist, offs, cursor, A);
    scatter_kernel<<<(E + 255) / 256, 256>>>(src, dst, r_ij, cursor, erec, E);

    // ---- stream 1: weight fp16 pre-convert (1 launch) + actv MLP ----
    {
        int total = NCH * HID / 2 + 2 * (HID * HID / 2);
        convert_w3<<<(total + 255) / 256, 256, 0, s1>>>(aW1, aW2, aW3, w1H, w2H, w3H);
    }
    fused_mlp_actv<<<(BA + 63) / 64, 256, SMEM_MLP, s1>>>(
        x_a, w1H, ab1, w2H, ab2, w3H, ab3, axH, BA);

    // ---- stream 2: dist-table build (FFMA pipe) ----
    encode_table<<<(TBL * 64 + 255) / 256, 256, 0, s2>>>(enc);
    mlp_small<64,  true,  false><<<TBL / 16, 256, 0, s2>>>(enc,  dW1, db1, tmpA, TBL);
    mlp_small<256, true,  false><<<TBL / 16, 256, 0, s2>>>(tmpA, dW2, db2, tmpB, TBL);
    mlp_small<256, false, true ><<<TBL / 16, 256, 0, s2>>>(tmpB, dW3, db3, tblP, TBL);

    // ---- join ----
    cudaEventRecord(ev1, s1);
    cudaEventRecord(ev2, s2);
    cudaStreamWaitEvent(0, ev1, 0);
    cudaStreamWaitEvent(0, ev2, 0);

    // ---- epilogue on origin stream ----
    epilogue_quad<<<A, 256>>>(tblP, axH, erec, offs, out_a, out_v, A);
}